// round 7
// baseline (speedup 1.0000x reference)
#include <cuda_runtime.h>
#include <cstdint>

// Problem constants
#define B 64
#define S 128
#define L 1024
#define H 512
#define E 256
#define V 64

// ---------------------------------------------------------------------------
// Scratch (single __device__ symbol; no allocation anywhere)
// ---------------------------------------------------------------------------
struct Scratch {
    float h0[2][B * H], c0[2][B * H];   // attention LSTM state (ping-pong)
    float h1[2][B * H], c1[2][B * H];   // rnn layer 0
    float h2[2][B * H], c2[2][B * H];   // rnn layer 1
    float r[B * H];                     // softmax-weighted sum of encoder_h
    float q[B * H];                     // query = P @ h2 + p0
    float hidden[B * H];                // MLP hidden
    float P[H * H];                     // Wh_w^T @ Ws_w
    float p0[H];                        // Wh_w^T @ Ws_b
    float A2[4 * H * H];                // att Wih[:,E:E+H] @ Wh_w  (ctx fold)
    float cbias[4 * H];                 // att Wih[:,E:E+H] @ Wh_b
    float w1b[H * H];                   // W1[:,H:2H] @ Wh_w
    float b1p[H];                       // b1 + W1[:,H:2H] @ Wh_b
    float am[B * 16], az[B * 16];       // per-chunk softmax max / sum
    float ar[B * 16 * H];               // per-chunk weighted partial sums
    int yflag;                          // 1 if y is int64, 0 if int32
};
__device__ Scratch g_s;
__device__ unsigned g_count;            // grid-barrier monotonic counter

// ---------------------------------------------------------------------------
// Grid-wide barrier: monotonic counter, no reset race. g_count zeroed by
// zero_kernel before the persistent kernel each replay. All blocks call the
// same number of times -> target k advances identically everywhere.
// ---------------------------------------------------------------------------
__device__ __forceinline__ void grid_sync(int nblk, unsigned& k) {
    k += (unsigned)nblk;
    __syncthreads();
    if (threadIdx.x == 0) {
        __threadfence();                          // release this block's writes
        atomicAdd(&g_count, 1u);
        while (*((volatile unsigned*)&g_count) < k) __nanosleep(64);
        __threadfence();                          // acquire others' writes
    }
    __syncthreads();
}

// ---------------------------------------------------------------------------
// y dtype detection: values in [0,64) -> if int64 (LE), odd int32 words are 0.
// ---------------------------------------------------------------------------
__global__ void detect_y_kernel(const void* y) {
    if (threadIdx.x == 0 && blockIdx.x == 0) {
        const int* yi = (const int*)y;
        int f = 1;
        for (int i = 0; i < 128; i++) {
            if (yi[2 * i + 1] != 0) { f = 0; break; }
        }
        g_s.yflag = f;
    }
}

__global__ void zero_kernel() {
    int i = blockIdx.x * blockDim.x + threadIdx.x;
    if (i == 0) g_count = 0u;
    if (i < B * H) {
        g_s.h0[0][i] = 0.f; g_s.c0[0][i] = 0.f;
        g_s.h1[0][i] = 0.f; g_s.c1[0][i] = 0.f;
        g_s.h2[0][i] = 0.f; g_s.c2[0][i] = 0.f;
        g_s.r[i] = 0.f;                  // t=0: ctx-region contribution = 0
    }
}

// ---------------------------------------------------------------------------
// One-time precompute kernels (small, run once per replay)
// ---------------------------------------------------------------------------
__global__ void prep_P_kernel(const float* __restrict__ Wh,
                              const float* __restrict__ Ws) {
    __shared__ float As[32][33];
    __shared__ float Bs[32][33];
    int tid = threadIdx.x;
    int tx = tid & 31, ty = tid >> 5;
    int j0 = blockIdx.y * 32, k0 = blockIdx.x * 32;
    float acc[4] = {0.f, 0.f, 0.f, 0.f};
    for (int i0 = 0; i0 < H; i0 += 32) {
        #pragma unroll
        for (int u = 0; u < 4; u++) {
            int idx = tid + u * 256;
            int ii = idx >> 5, cc = idx & 31;
            As[ii][cc] = Wh[(i0 + ii) * H + j0 + cc];
            Bs[ii][cc] = Ws[(i0 + ii) * H + k0 + cc];
        }
        __syncthreads();
        #pragma unroll
        for (int ii = 0; ii < 32; ii++) {
            float bv = Bs[ii][tx];
            #pragma unroll
            for (int rr = 0; rr < 4; rr++) acc[rr] += As[ii][ty + 8 * rr] * bv;
        }
        __syncthreads();
    }
    #pragma unroll
    for (int rr = 0; rr < 4; rr++)
        g_s.P[(j0 + ty + 8 * rr) * H + k0 + tx] = acc[rr];
}

__global__ void prep_p0_kernel(const float* __restrict__ Wh,
                               const float* __restrict__ Wsb) {
    int j = blockIdx.x * blockDim.x + threadIdx.x;
    if (j < H) {
        float a = 0.f;
        for (int i = 0; i < H; i++) a += Wh[i * H + j] * Wsb[i];
        g_s.p0[j] = a;
    }
}

// C[m][n] = sum_k A[m*lda + offA + k] * Bm[k*ldb + n], K = 512
__global__ void prep_gemm_kernel(const float* __restrict__ A, int lda, int offA,
                                 const float* __restrict__ Bm, int ldb,
                                 float* __restrict__ Cm, int ldc) {
    __shared__ float As[32][33];
    __shared__ float Bs[32][33];
    int tid = threadIdx.x;
    int tx = tid & 31, ty = tid >> 5;
    int n0 = blockIdx.x * 32, m0 = blockIdx.y * 32;
    float acc[4] = {0.f, 0.f, 0.f, 0.f};
    for (int k0 = 0; k0 < H; k0 += 32) {
        #pragma unroll
        for (int u = 0; u < 4; u++) {
            int idx = tid + u * 256;
            int rr = idx >> 5, cc = idx & 31;
            As[rr][cc] = A[(m0 + rr) * lda + offA + k0 + cc];
            Bs[rr][cc] = Bm[(k0 + rr) * ldb + n0 + cc];
        }
        __syncthreads();
        #pragma unroll
        for (int kk = 0; kk < 32; kk++) {
            float bv = Bs[kk][tx];
            #pragma unroll
            for (int rr = 0; rr < 4; rr++) acc[rr] += As[ty + 8 * rr][kk] * bv;
        }
        __syncthreads();
    }
    #pragma unroll
    for (int rr = 0; rr < 4; rr++)
        Cm[(m0 + ty + 8 * rr) * ldc + n0 + tx] = acc[rr];
}

__global__ void prep_cbias_kernel(const float* __restrict__ Wih,
                                  const float* __restrict__ Whb) {
    int j = blockIdx.x * blockDim.x + threadIdx.x;
    if (j < 4 * H) {
        float a = 0.f;
        for (int k = 0; k < H; k++) a += Wih[j * (E + H) + E + k] * Whb[k];
        g_s.cbias[j] = a;
    }
}

__global__ void prep_b1p_kernel(const float* __restrict__ W1,
                                const float* __restrict__ b1,
                                const float* __restrict__ Whb) {
    int n = blockIdx.x * blockDim.x + threadIdx.x;
    if (n < H) {
        float a = b1[n];
        for (int k = 0; k < H; k++) a += W1[n * 2 * H + H + k] * Whb[k];
        g_s.b1p[n] = a;
    }
}

// ---------------------------------------------------------------------------
// Register-staging helpers for the LSTM software pipeline
// ---------------------------------------------------------------------------
template <bool ATT, int Kx>
__device__ __forceinline__ void load_x_regs(float (&xr)[32], int k0, int tid,
                                            const int* ysm,
                                            const float* __restrict__ emb,
                                            const float* __restrict__ xlow,
                                            const float* __restrict__ hprev) {
    #pragma unroll
    for (int u = 0; u < 32; u++) {
        int idx = tid + u * 256;
        int bb = idx >> 7, kk = idx & 127;
        int k = k0 + kk;
        float v;
        if (ATT) {
            if (k < E)       v = emb[ysm[bb] * E + k];
            else if (k < Kx) v = g_s.r[bb * H + (k - E)];
            else             v = hprev[bb * H + (k - Kx)];
        } else {
            if (k < Kx) v = xlow[bb * H + k];
            else        v = hprev[bb * H + (k - Kx)];
        }
        xr[u] = v;
    }
}

template <bool ATT, int Kx>
__device__ __forceinline__ void load_w_regs(float (&wr)[8], int k0, int tid,
                                            int jbase,
                                            const float* __restrict__ Wih,
                                            const float* __restrict__ A2p,
                                            const float* __restrict__ Whh) {
    #pragma unroll
    for (int u = 0; u < 8; u++) {
        int idx = tid + u * 256;
        int r16 = idx >> 7, kk = idx & 127;
        int g = r16 >> 2, jj = r16 & 3;
        int row = g * H + jbase + jj;
        int k = k0 + kk;
        float wv;
        if (ATT) {
            if (k < E)       wv = Wih[row * (E + H) + k];
            else if (k < Kx) wv = A2p[row * H + (k - E)];
            else             wv = Whh[row * H + (k - Kx)];
        } else {
            if (k < Kx) wv = Wih[row * H + k];
            else        wv = Whh[row * H + (k - Kx)];
        }
        wr[u] = wv;
    }
}

// ---------------------------------------------------------------------------
// LSTM stage body (one j-quad tile). Block = 64 batch x 4 gate-quads.
// ATT=true : x = [emb(y[:,t]) | r_prev (A2 ctx-fold) | h_prev], K=1280
// ATT=false: x = [x_low | h_prev], K=1024
// ---------------------------------------------------------------------------
template <bool ATT>
__device__ void lstm_body(int jbase, int t,
                          const float* __restrict__ xlow,
                          const void* __restrict__ yptr,
                          const float* __restrict__ emb,
                          const float* __restrict__ hprev,
                          const float* __restrict__ cprev,
                          const float* __restrict__ Wih,
                          const float* __restrict__ A2p,
                          const float* __restrict__ Whh,
                          const float* __restrict__ bih,
                          const float* __restrict__ bhh,
                          float* __restrict__ hout,
                          float* __restrict__ cout,
                          float* sm_base) {
    constexpr int Kx = ATT ? (E + H) : H;
    constexpr int Ktot = Kx + H;            // 1280 or 1024
    constexpr int NCH = Ktot / 128;
    float (*xs)[132] = (float (*)[132])sm_base;                 // 64 x 132
    float (*ws)[128] = (float (*)[128])(sm_base + 64 * 132);    // 16 x 128
    int* ysm = (int*)(sm_base + 64 * 132 + 16 * 128);           // 64 ints

    int tid = threadIdx.x;
    int b = tid & 63, jq = tid >> 6;

    if (ATT) {
        if (tid < B)
            ysm[tid] = g_s.yflag ? (int)((const long long*)yptr)[tid * S + t]
                                 : ((const int*)yptr)[tid * S + t];
        __syncthreads();
    }

    float xr[32], wr[8];
    load_x_regs<ATT, Kx>(xr, 0, tid, ysm, emb, xlow, hprev);
    load_w_regs<ATT, Kx>(wr, 0, tid, jbase, Wih, A2p, Whh);

    float ai = 0.f, af = 0.f, ag = 0.f, ao = 0.f;

    #pragma unroll
    for (int ch = 0; ch < NCH; ch++) {
        #pragma unroll
        for (int u = 0; u < 32; u++) {
            int idx = tid + u * 256;
            xs[idx >> 7][idx & 127] = xr[u];
        }
        #pragma unroll
        for (int u = 0; u < 8; u++) {
            int idx = tid + u * 256;
            ws[idx >> 7][idx & 127] = wr[u];
        }
        __syncthreads();
        if (ch + 1 < NCH) {   // prefetch next chunk; overlaps with compute
            load_x_regs<ATT, Kx>(xr, (ch + 1) * 128, tid, ysm, emb, xlow, hprev);
            load_w_regs<ATT, Kx>(wr, (ch + 1) * 128, tid, jbase, Wih, A2p, Whh);
        }
        #pragma unroll
        for (int kk = 0; kk < 128; kk += 4) {
            float4 xv = *(const float4*)&xs[b][kk];
            float4 wi = *(const float4*)&ws[jq][kk];
            float4 wf = *(const float4*)&ws[4 + jq][kk];
            float4 wg = *(const float4*)&ws[8 + jq][kk];
            float4 wo = *(const float4*)&ws[12 + jq][kk];
            ai += xv.x * wi.x + xv.y * wi.y + xv.z * wi.z + xv.w * wi.w;
            af += xv.x * wf.x + xv.y * wf.y + xv.z * wf.z + xv.w * wf.w;
            ag += xv.x * wg.x + xv.y * wg.y + xv.z * wg.z + xv.w * wg.w;
            ao += xv.x * wo.x + xv.y * wo.y + xv.z * wo.z + xv.w * wo.w;
        }
        __syncthreads();
    }

    int j = jbase + jq;
    float ei = 0.f, ef = 0.f, eg = 0.f, eo = 0.f;
    if (ATT && t > 0) {   // ctx-fold bias: reference's initial att is exactly 0
        ei = g_s.cbias[j];
        ef = g_s.cbias[j + H];
        eg = g_s.cbias[j + 2 * H];
        eo = g_s.cbias[j + 3 * H];
    }
    float gi = ai + bih[j]         + bhh[j]         + ei;
    float gf = af + bih[j + H]     + bhh[j + H]     + ef;
    float gg = ag + bih[j + 2 * H] + bhh[j + 2 * H] + eg;
    float go = ao + bih[j + 3 * H] + bhh[j + 3 * H] + eo;
    float si = 1.f / (1.f + expf(-gi));
    float sf = 1.f / (1.f + expf(-gf));
    float so = 1.f / (1.f + expf(-go));
    float c2 = sf * cprev[b * H + j] + si * tanhf(gg);
    float h2 = so * tanhf(c2);
    cout[b * H + j] = c2;
    hout[b * H + j] = h2;
}

// ---------------------------------------------------------------------------
// Linear stage body (one n-quad tile), split weights for ctx-fold:
// out[b,n] = act(bias[n] + sum_{k<K1} x1[b,k] Wa[n,k] + sum x2[b,k] Wb[n,k])
// ---------------------------------------------------------------------------
template <bool RELU>
__device__ void linear_body(int nbase,
                            const float* __restrict__ x1, int K1,
                            const float* __restrict__ x2,
                            const float* __restrict__ Wa, int ldwa,
                            const float* __restrict__ Wb, int ldwb,
                            int Ktot,
                            const float* __restrict__ bias,
                            float* __restrict__ outp, int ldo, int off,
                            float* sm_base) {
    float (*xs)[132] = (float (*)[132])sm_base;
    float (*ws)[128] = (float (*)[128])(sm_base + 64 * 132);
    int tid = threadIdx.x;
    int b = tid & 63, nq = tid >> 6;
    int K2 = Ktot - K1;
    int NCH = Ktot >> 7;

    float xr[32], wr[2];
    #pragma unroll
    for (int u = 0; u < 32; u++) {
        int idx = tid + u * 256;
        int bb = idx >> 7, kk = idx & 127;
        xr[u] = (kk < K1) ? x1[bb * K1 + kk] : x2[bb * K2 + (kk - K1)];
    }
    #pragma unroll
    for (int u = 0; u < 2; u++) {
        int idx = tid + u * 256;
        int rr = idx >> 7, kk = idx & 127;
        wr[u] = (kk < K1) ? Wa[(nbase + rr) * ldwa + kk]
                          : Wb[(nbase + rr) * ldwb + (kk - K1)];
    }

    float acc = 0.f;
    for (int ch = 0; ch < NCH; ch++) {
        #pragma unroll
        for (int u = 0; u < 32; u++) {
            int idx = tid + u * 256;
            xs[idx >> 7][idx & 127] = xr[u];
        }
        #pragma unroll
        for (int u = 0; u < 2; u++) {
            int idx = tid + u * 256;
            ws[idx >> 7][idx & 127] = wr[u];
        }
        __syncthreads();
        if (ch + 1 < NCH) {
            int k0 = (ch + 1) * 128;
            #pragma unroll
            for (int u = 0; u < 32; u++) {
                int idx = tid + u * 256;
                int bb = idx >> 7, kk = idx & 127;
                int k = k0 + kk;
                xr[u] = (k < K1) ? x1[bb * K1 + k] : x2[bb * K2 + (k - K1)];
            }
            #pragma unroll
            for (int u = 0; u < 2; u++) {
                int idx = tid + u * 256;
                int rr = idx >> 7, kk = idx & 127;
                int k = k0 + kk;
                wr[u] = (k < K1) ? Wa[(nbase + rr) * ldwa + k]
                                 : Wb[(nbase + rr) * ldwb + (k - K1)];
            }
        }
        #pragma unroll
        for (int kk = 0; kk < 128; kk += 4) {
            float4 xv = *(const float4*)&xs[b][kk];
            float4 w = *(const float4*)&ws[nq][kk];
            acc += xv.x * w.x + xv.y * w.y + xv.z * w.z + xv.w * w.w;
        }
        __syncthreads();
    }
    int n = nbase + nq;
    acc += bias[n];
    if (RELU) acc = fmaxf(acc, 0.f);
    outp[b * ldo + off + n] = acc;
}

// ---------------------------------------------------------------------------
// Flash-style attention chunk body: (c, bq) stages enc[bq, c*64:(c+1)*64, :]
// into smem once, computes e, chunk-local (m, Z), unnormalized weighted sum.
// ---------------------------------------------------------------------------
__device__ void attn_body(int c, int bq, const float* __restrict__ enc,
                          float* sm_base) {
    float* s_enc = sm_base;                  // 64 * 512
    float* s_q = sm_base + 64 * H;           // 512
    float* s_e = s_q + H;                    // 64
    float* s_p = s_e + 64;                   // 64
    float* s_m = s_p + 64;                   // 1

    int tid = threadIdx.x;
    const float4* src = (const float4*)(enc + ((size_t)bq * L + (size_t)c * 64) * H);
    float4* dst = (float4*)s_enc;
    #pragma unroll 8
    for (int u = 0; u < 32; u++) dst[tid + u * 256] = src[tid + u * 256];
    if (tid < 128) ((float4*)s_q)[tid] = ((const float4*)(g_s.q + bq * H))[tid];
    __syncthreads();

    int w = tid >> 5, lane = tid & 31;
    for (int l = w; l < 64; l += 8) {
        float sum = 0.f;
        #pragma unroll
        for (int it = 0; it < 16; it++) {
            int j = lane + it * 32;
            sum += s_q[j] * s_enc[l * H + j];
        }
        #pragma unroll
        for (int o = 16; o > 0; o >>= 1) sum += __shfl_xor_sync(0xffffffffu, sum, o);
        if (lane == 0) s_e[l] = sum;
    }
    __syncthreads();
    if (tid < 32) {
        float m = fmaxf(s_e[lane], s_e[lane + 32]);
        #pragma unroll
        for (int o = 16; o > 0; o >>= 1) m = fmaxf(m, __shfl_xor_sync(0xffffffffu, m, o));
        if (lane == 0) *s_m = m;
    }
    __syncthreads();
    if (tid < 64) s_p[tid] = expf(s_e[tid] - *s_m);
    __syncthreads();
    if (tid < 32) {
        float z = s_p[lane] + s_p[lane + 32];
        #pragma unroll
        for (int o = 16; o > 0; o >>= 1) z += __shfl_xor_sync(0xffffffffu, z, o);
        if (lane == 0) {
            g_s.am[bq * 16 + c] = *s_m;
            g_s.az[bq * 16 + c] = z;
        }
    }
    float* rdst = g_s.ar + ((size_t)bq * 16 + c) * H;
    #pragma unroll
    for (int rr = 0; rr < 2; rr++) {
        int j = tid + rr * 256;
        float acc = 0.f;
        #pragma unroll 8
        for (int l = 0; l < 64; l++) acc += s_p[l] * s_enc[l * H + j];
        rdst[j] = acc;
    }
    __syncthreads();   // smem reused by next task / stage
}

// Merge 16 chunk partials for one batch element -> r[bq, :]
__device__ void reduce_body(int bq, float* sm_base) {
    float* sw = sm_base;   // 16 floats
    int tid = threadIdx.x;
    if (tid == 0) {
        float m = -1e30f;
        for (int cc = 0; cc < 16; cc++) m = fmaxf(m, g_s.am[bq * 16 + cc]);
        float Z = 0.f;
        for (int cc = 0; cc < 16; cc++)
            Z += expf(g_s.am[bq * 16 + cc] - m) * g_s.az[bq * 16 + cc];
        for (int cc = 0; cc < 16; cc++)
            sw[cc] = expf(g_s.am[bq * 16 + cc] - m) / Z;
    }
    __syncthreads();
    for (int j = tid; j < H; j += 256) {
        float acc = 0.f;
        #pragma unroll
        for (int cc = 0; cc < 16; cc++)
            acc += sw[cc] * g_s.ar[((size_t)bq * 16 + cc) * H + j];
        g_s.r[bq * H + j] = acc;
    }
    __syncthreads();
}

// ---------------------------------------------------------------------------
// Persistent decoder: the entire 128-step loop in ONE kernel.
// Grid = nblk (<= 128 <= #SMs) blocks x 256 threads, 1 block/SM co-resident.
// ---------------------------------------------------------------------------
__global__ void __launch_bounds__(256, 1)
decoder_kernel(int nblk,
               const void* __restrict__ yptr,
               const float* __restrict__ enc,
               const float* __restrict__ emb,
               const float* __restrict__ aWih, const float* __restrict__ aWhh,
               const float* __restrict__ abih, const float* __restrict__ abhh,
               const float* __restrict__ rWih, const float* __restrict__ rWhh,
               const float* __restrict__ rbih, const float* __restrict__ rbhh,
               const float* __restrict__ W1, const float* __restrict__ W2,
               const float* __restrict__ b2,
               float* __restrict__ out) {
    extern __shared__ __align__(16) float sm[];
    const int bid = blockIdx.x;
    unsigned bk = 0;

    for (int t = 0; t < S; t++) {
        int rp = t & 1, wp = rp ^ 1;

        // S1: attention LSTM (ctx folded via A2 @ r_prev + cbias)
        for (int task = bid; task < 128; task += nblk)
            lstm_body<true>(task * 4, t, nullptr, yptr, emb,
                            g_s.h0[rp], g_s.c0[rp],
                            aWih, g_s.A2, aWhh, abih, abhh,
                            g_s.h0[wp], g_s.c0[wp], sm);
        grid_sync(nblk, bk);

        // S2: rnn layer 0
        for (int task = bid; task < 128; task += nblk)
            lstm_body<false>(task * 4, t, g_s.h0[wp], nullptr, nullptr,
                             g_s.h1[rp], g_s.c1[rp],
                             rWih, nullptr, rWhh, rbih, rbhh,
                             g_s.h1[wp], g_s.c1[wp], sm);
        grid_sync(nblk, bk);

        // S3: rnn layer 1
        for (int task = bid; task < 128; task += nblk)
            lstm_body<false>(task * 4, t, g_s.h1[wp], nullptr, nullptr,
                             g_s.h2[rp], g_s.c2[rp],
                             rWih + 4 * H * H, nullptr, rWhh + 4 * H * H,
                             rbih + 4 * H, rbhh + 4 * H,
                             g_s.h2[wp], g_s.c2[wp], sm);
        grid_sync(nblk, bk);

        // S4: q = P @ h2 + p0
        for (int task = bid; task < 128; task += nblk)
            linear_body<false>(task * 4, g_s.h2[wp], H, nullptr,
                               g_s.P, H, nullptr, 0, H,
                               g_s.p0, g_s.q, H, 0, sm);
        grid_sync(nblk, bk);

        // S5: flash attention chunks (1024 tasks)
        for (int task = bid; task < 1024; task += nblk)
            attn_body(task & 15, task >> 4, enc, sm);
        grid_sync(nblk, bk);

        // S6: softmax merge -> r
        for (int task = bid; task < B; task += nblk)
            reduce_body(task, sm);
        grid_sync(nblk, bk);

        // S7: hidden = relu(W1a@h2 + (W1b@Whw)@r + b1')
        for (int task = bid; task < 128; task += nblk)
            linear_body<true>(task * 4, g_s.h2[wp], H, g_s.r,
                              W1, 2 * H, g_s.w1b, H, 2 * H,
                              g_s.b1p, g_s.hidden, H, 0, sm);
        grid_sync(nblk, bk);

        // S8: logits -> out[(b*S + t)*V + n]  (no barrier; next S1 is hazard-free)
        for (int task = bid; task < V / 4; task += nblk)
            linear_body<false>(task * 4, g_s.hidden, H, nullptr,
                               W2, H, nullptr, 0, H,
                               b2, out, S * V, t * V, sm);
    }
}

// ---------------------------------------------------------------------------
// Host launcher
// ---------------------------------------------------------------------------
extern "C" void kernel_launch(void* const* d_in, const int* in_sizes, int n_in,
                              void* d_out, int out_size) {
    const void*  y    = d_in[0];
    const float* enc  = (const float*)d_in[1];
    const float* emb  = (const float*)d_in[2];
    const float* aWih = (const float*)d_in[3];
    const float* aWhh = (const float*)d_in[4];
    const float* abih = (const float*)d_in[5];
    const float* abhh = (const float*)d_in[6];
    const float* rWih = (const float*)d_in[7];
    const float* rWhh = (const float*)d_in[8];
    const float* rbih = (const float*)d_in[9];
    const float* rbhh = (const float*)d_in[10];
    const float* Wsw  = (const float*)d_in[11];
    const float* Wsb  = (const float*)d_in[12];
    const float* Whw  = (const float*)d_in[13];
    const float* Whb  = (const float*)d_in[14];
    const float* W1   = (const float*)d_in[15];
    const float* b1   = (const float*)d_in[16];
    const float* W2   = (const float*)d_in[17];
    const float* b2   = (const float*)d_in[18];
    float* out = (float*)d_out;

    Scratch* s = nullptr;
    cudaGetSymbolAddress((void**)&s, g_s);

    // smem: max(attention 64*512+512+64+64+1, lstm 64*132+16*128+64) floats
    const int SMEM_BYTES = (64 * H + H + 64 + 64 + 16) * (int)sizeof(float);
    static int configured = -1;
    if (configured < 0) {
        cudaFuncSetAttribute(decoder_kernel,
                             cudaFuncAttributeMaxDynamicSharedMemorySize,
                             SMEM_BYTES);
        configured = 1;
    }

    int dev = 0;
    cudaGetDevice(&dev);
    int sms = 128;
    cudaDeviceGetAttribute(&sms, cudaDevAttrMultiProcessorCount, dev);
    int nblk = sms < 128 ? sms : 128;   // co-residency guaranteed: 1 block/SM

    // Prep (8 tiny nodes) + 1 persistent node => 9-node graph
    detect_y_kernel<<<1, 32>>>(y);
    zero_kernel<<<(B * H + 255) / 256, 256>>>();
    prep_P_kernel<<<dim3(16, 16), 256>>>(Whw, Wsw);
    prep_p0_kernel<<<2, 256>>>(Whw, Wsb);
    prep_gemm_kernel<<<dim3(16, 64), 256>>>(aWih, E + H, E, Whw, H, s->A2, H);
    prep_gemm_kernel<<<dim3(16, 16), 256>>>(W1, 2 * H, H, Whw, H, s->w1b, H);
    prep_cbias_kernel<<<8, 256>>>(aWih, Whb);
    prep_b1p_kernel<<<2, 256>>>(W1, b1, Whb);

    decoder_kernel<<<nblk, 256, SMEM_BYTES>>>(
        nblk, y, enc, emb,
        aWih, aWhh, abih, abhh,
        rWih, rWhh, rbih, rbhh,
        W1, W2, b2, out);
}

// round 8
// speedup vs baseline: 1.6785x; 1.6785x over previous
#include <cuda_runtime.h>
#include <cstdint>

#define B 64
#define S 128
#define L 1024
#define H 512
#define E 256
#define V 64

// ---------------------------------------------------------------------------
struct Scratch {
    float h0[2][B * H], c0[2][B * H];
    float h1[2][B * H], c1[2][B * H];
    float h2[2][B * H], c2[2][B * H];
    float r[B * H];                     // merged attention context (pre-Wh)
    float q[B * H];
    float hidden[B * H];
    float P[H * H], p0[H];              // folded mlp_s/mlp_h query projection
    float A2[4 * H * H], cbias[4 * H];  // ctx fold into att LSTM
    float w1b[H * H], b1p[H];           // ctx fold into MLP
    float EW[V * 4 * H];                // emb @ attWih[:, :E]^T + bih + bhh
    float am[B * 2], az[B * 2];         // per-half softmax stats
    float ar[B * 2 * H];                // per-half unnormalized weighted sums
    int yflag;
};
__device__ Scratch g_s;
__device__ unsigned g_count;

// Packed f32x2 FMA (sm_100+): two fp32 FMAs per instruction
__device__ __forceinline__ void fma2(unsigned long long& a,
                                     unsigned long long x,
                                     unsigned long long w) {
    asm("fma.rn.f32x2 %0, %1, %2, %3;" : "=l"(a) : "l"(x), "l"(w), "l"(a));
}
__device__ __forceinline__ float red2(unsigned long long a) {
    float lo, hi;
    asm("mov.b64 {%0,%1}, %2;" : "=f"(lo), "=f"(hi) : "l"(a));
    return lo + hi;
}

// Grid barrier: monotonic counter, plain spin. Zeroed by init_kernel.
__device__ __forceinline__ void grid_sync(int nblk, unsigned& k) {
    k += (unsigned)nblk;
    __syncthreads();
    if (threadIdx.x == 0) {
        __threadfence();
        atomicAdd(&g_count, 1u);
        while (*((volatile unsigned*)&g_count) < k) { }
        __threadfence();
    }
    __syncthreads();
}

// cp.async: one 32x512 fp32 tile (64KB) per block call
__device__ __forceinline__ void copy_tile_async(float* dst,
                                                const float* __restrict__ src,
                                                int tid) {
    unsigned d = (unsigned)__cvta_generic_to_shared(dst);
    #pragma unroll
    for (int u = 0; u < 16; u++) {
        int fo = (tid + u * 256) * 4;
        asm volatile("cp.async.cg.shared.global [%0], [%1], 16;"
                     :: "r"(d + fo * 4), "l"(src + fo));
    }
}
#define CP_COMMIT() asm volatile("cp.async.commit_group;")
template <int N>
__device__ __forceinline__ void cp_wait() {
    asm volatile("cp.async.wait_group %0;" :: "n"(N));
}

// Shared-memory views (floats)
#define SM_XS 0
#define SM_WS (64 * 132)
#define SM_SW (SM_WS + 16 * 128)
#define SM_YS (SM_SW + 128)
#define SM_ABUF 0
#define SM_AQ (2 * 32 * 512)
#define SM_AE (SM_AQ + 512)
#define SM_AST (SM_AE + 32)
#define SM_AP (SM_AST + 4)
#define SMEM_FLOATS (SM_AP + 48)

// ---------------------------------------------------------------------------
__global__ void init_kernel(const void* y) {
    int i = blockIdx.x * blockDim.x + threadIdx.x;
    if (i == 0) {
        g_count = 0u;
        const int* yi = (const int*)y;
        int f = 1;
        for (int k = 0; k < 128; k++)
            if (yi[2 * k + 1] != 0) { f = 0; break; }
        g_s.yflag = f;
    }
    if (i < B * H) {
        g_s.h0[0][i] = 0.f; g_s.c0[0][i] = 0.f;
        g_s.h1[0][i] = 0.f; g_s.c1[0][i] = 0.f;
        g_s.h2[0][i] = 0.f; g_s.c2[0][i] = 0.f;
        g_s.r[i] = 0.f;                 // t=0 ctx contribution is exactly 0
    }
}

// ---------------------------------------------------------------------------
// Preamble tile bodies (32x32 tiles, 256 threads, trailing sync for reuse)
// ---------------------------------------------------------------------------
// P[j][k] = sum_i Wh[i][j] * Ws[i][k]
__device__ void tileP_body(int j0, int k0, const float* __restrict__ Wh,
                           const float* __restrict__ Ws, float* sm) {
    float (*As)[33] = (float(*)[33])sm;
    float (*Bs)[33] = (float(*)[33])(sm + 32 * 33);
    int tid = threadIdx.x, tx = tid & 31, ty = tid >> 5;
    float acc[4] = {0.f, 0.f, 0.f, 0.f};
    for (int i0 = 0; i0 < H; i0 += 32) {
        #pragma unroll
        for (int u = 0; u < 4; u++) {
            int idx = tid + u * 256, ii = idx >> 5, cc = idx & 31;
            As[ii][cc] = Wh[(i0 + ii) * H + j0 + cc];
            Bs[ii][cc] = Ws[(i0 + ii) * H + k0 + cc];
        }
        __syncthreads();
        #pragma unroll
        for (int ii = 0; ii < 32; ii++) {
            float bv = Bs[ii][tx];
            #pragma unroll
            for (int rr = 0; rr < 4; rr++) acc[rr] += As[ii][ty + 8 * rr] * bv;
        }
        __syncthreads();
    }
    #pragma unroll
    for (int rr = 0; rr < 4; rr++)
        g_s.P[(j0 + ty + 8 * rr) * H + k0 + tx] = acc[rr];
    __syncthreads();
}

// C[m][n] = sum_k A[m*lda + offA + k] * Bm[k*ldb + n], K=512
__device__ void tileAB_body(const float* __restrict__ A, int lda, int offA,
                            const float* __restrict__ Bm, int ldb,
                            float* __restrict__ Cm, int ldc,
                            int n0, int m0, float* sm) {
    float (*As)[33] = (float(*)[33])sm;
    float (*Bs)[33] = (float(*)[33])(sm + 32 * 33);
    int tid = threadIdx.x, tx = tid & 31, ty = tid >> 5;
    float acc[4] = {0.f, 0.f, 0.f, 0.f};
    for (int k0 = 0; k0 < H; k0 += 32) {
        #pragma unroll
        for (int u = 0; u < 4; u++) {
            int idx = tid + u * 256, rr = idx >> 5, cc = idx & 31;
            As[rr][cc] = A[(m0 + rr) * lda + offA + k0 + cc];
            Bs[rr][cc] = Bm[(k0 + rr) * ldb + n0 + cc];
        }
        __syncthreads();
        #pragma unroll
        for (int kk = 0; kk < 32; kk++) {
            float bv = Bs[kk][tx];
            #pragma unroll
            for (int rr = 0; rr < 4; rr++) acc[rr] += As[ty + 8 * rr][kk] * bv;
        }
        __syncthreads();
    }
    #pragma unroll
    for (int rr = 0; rr < 4; rr++)
        Cm[(m0 + ty + 8 * rr) * ldc + n0 + tx] = acc[rr];
    __syncthreads();
}

// EW[v][j] = sum_k emb[v][k]*attWih[j][k] + bih[j] + bhh[j]  (K=256)
__device__ void tileEW_body(const float* __restrict__ emb,
                            const float* __restrict__ Wih,
                            const float* __restrict__ bih,
                            const float* __restrict__ bhh,
                            int v0, int j0, float* sm) {
    float (*As)[33] = (float(*)[33])sm;
    float (*Bs)[33] = (float(*)[33])(sm + 32 * 33);
    int tid = threadIdx.x, tx = tid & 31, ty = tid >> 5;
    float acc[4] = {0.f, 0.f, 0.f, 0.f};
    for (int k0 = 0; k0 < E; k0 += 32) {
        #pragma unroll
        for (int u = 0; u < 4; u++) {
            int idx = tid + u * 256, rr = idx >> 5, cc = idx & 31;
            As[rr][cc] = emb[(v0 + rr) * E + k0 + cc];
            Bs[rr][cc] = Wih[(j0 + rr) * (E + H) + k0 + cc];
        }
        __syncthreads();
        #pragma unroll
        for (int kk = 0; kk < 32; kk++) {
            #pragma unroll
            for (int rr = 0; rr < 4; rr++)
                acc[rr] += As[ty + 8 * rr][kk] * Bs[tx][kk];
        }
        __syncthreads();
    }
    #pragma unroll
    for (int rr = 0; rr < 4; rr++) {
        int v = v0 + ty + 8 * rr, j = j0 + tx;
        g_s.EW[v * (4 * H) + j] = acc[rr] + bih[j] + bhh[j];
    }
    __syncthreads();
}

__device__ void vec_p0(int part, const float* __restrict__ Wh,
                       const float* __restrict__ Wsb) {
    int j = part * 256 + threadIdx.x;
    float a = 0.f;
    for (int i = 0; i < H; i++) a += Wh[i * H + j] * Wsb[i];
    g_s.p0[j] = a;
}
__device__ void vec_cbias(int part, const float* __restrict__ Wih,
                          const float* __restrict__ Whb) {
    int j = part * 256 + threadIdx.x;
    float a = 0.f;
    for (int k = 0; k < H; k++) a += Wih[j * (E + H) + E + k] * Whb[k];
    g_s.cbias[j] = a;
}
__device__ void vec_b1p(int part, const float* __restrict__ W1,
                        const float* __restrict__ b1,
                        const float* __restrict__ Whb) {
    int n = part * 256 + threadIdx.x;
    float a = b1[n];
    for (int k = 0; k < H; k++) a += W1[n * 2 * H + H + k] * Whb[k];
    g_s.b1p[n] = a;
}

// ---------------------------------------------------------------------------
// Uniform LSTM body, K = 1024: x = [xlo(512) | hprev(512)], W = [Wlo | Whh].
// first: epilogue adds EW[y] (+cbias for t>0) instead of bih+bhh.
// Block = 64 batch x 4 gate-quads; inner loop is k-packed FFMA2.
// ---------------------------------------------------------------------------
__device__ void lstm_body(int jbase, int first, int t,
                          const void* __restrict__ yptr,
                          const float* __restrict__ xlo,
                          const float* __restrict__ hprev,
                          const float* __restrict__ cprev,
                          const float* __restrict__ Wlo,
                          const float* __restrict__ Whh,
                          const float* __restrict__ bih,
                          const float* __restrict__ bhh,
                          float* __restrict__ hout,
                          float* __restrict__ cout, float* sm) {
    float (*xs)[132] = (float(*)[132])(sm + SM_XS);
    float (*ws)[128] = (float(*)[128])(sm + SM_WS);
    int* ysm = (int*)(sm + SM_YS);
    int tid = threadIdx.x, b = tid & 63, jq = tid >> 6;

    if (first && tid < B)
        ysm[tid] = g_s.yflag ? (int)((const long long*)yptr)[tid * S + t]
                             : ((const int*)yptr)[tid * S + t];

    float xr[32], wr[8];
    #pragma unroll
    for (int u = 0; u < 32; u++) {                 // chunk 0: k<128 -> xlo
        int idx = tid + u * 256;
        xr[u] = xlo[(idx >> 7) * H + (idx & 127)];
    }
    #pragma unroll
    for (int u = 0; u < 8; u++) {
        int idx = tid + u * 256, r16 = idx >> 7;
        int row = (r16 >> 2) * H + jbase + (r16 & 3);
        wr[u] = Wlo[row * H + (idx & 127)];
    }

    unsigned long long a0 = 0ull, a1 = 0ull, a2 = 0ull, a3 = 0ull;
    for (int ch = 0; ch < 8; ch++) {
        #pragma unroll
        for (int u = 0; u < 32; u++) {
            int idx = tid + u * 256;
            xs[idx >> 7][idx & 127] = xr[u];
        }
        #pragma unroll
        for (int u = 0; u < 8; u++) {
            int idx = tid + u * 256;
            ws[idx >> 7][idx & 127] = wr[u];
        }
        __syncthreads();
        if (ch < 7) {                              // prefetch next chunk
            int k0 = (ch + 1) * 128;
            #pragma unroll
            for (int u = 0; u < 32; u++) {
                int idx = tid + u * 256, bb = idx >> 7, k = k0 + (idx & 127);
                xr[u] = (k < H) ? xlo[bb * H + k] : hprev[bb * H + (k - H)];
            }
            #pragma unroll
            for (int u = 0; u < 8; u++) {
                int idx = tid + u * 256, r16 = idx >> 7;
                int row = (r16 >> 2) * H + jbase + (r16 & 3);
                int k = k0 + (idx & 127);
                wr[u] = (k < H) ? Wlo[row * H + k] : Whh[row * H + (k - H)];
            }
        }
        #pragma unroll
        for (int kk = 0; kk < 128; kk += 4) {
            ulonglong2 xv = *(const ulonglong2*)&xs[b][kk];
            ulonglong2 w0 = *(const ulonglong2*)&ws[jq][kk];
            ulonglong2 w1 = *(const ulonglong2*)&ws[4 + jq][kk];
            ulonglong2 w2 = *(const ulonglong2*)&ws[8 + jq][kk];
            ulonglong2 w3 = *(const ulonglong2*)&ws[12 + jq][kk];
            fma2(a0, xv.x, w0.x); fma2(a0, xv.y, w0.y);
            fma2(a1, xv.x, w1.x); fma2(a1, xv.y, w1.y);
            fma2(a2, xv.x, w2.x); fma2(a2, xv.y, w2.y);
            fma2(a3, xv.x, w3.x); fma2(a3, xv.y, w3.y);
        }
        __syncthreads();
    }

    int j = jbase + jq;
    float gi = red2(a0), gf = red2(a1), gg = red2(a2), go = red2(a3);
    if (first) {
        const float* ew = g_s.EW + ysm[b] * (4 * H);
        gi += ew[j];         gf += ew[j + H];
        gg += ew[j + 2 * H]; go += ew[j + 3 * H];
        if (t > 0) {
            gi += g_s.cbias[j];         gf += g_s.cbias[j + H];
            gg += g_s.cbias[j + 2 * H]; go += g_s.cbias[j + 3 * H];
        }
    } else {
        gi += bih[j] + bhh[j];
        gf += bih[j + H] + bhh[j + H];
        gg += bih[j + 2 * H] + bhh[j + 2 * H];
        go += bih[j + 3 * H] + bhh[j + 3 * H];
    }
    float si = 1.f / (1.f + expf(-gi));
    float sf = 1.f / (1.f + expf(-gf));
    float so = 1.f / (1.f + expf(-go));
    float cv = sf * cprev[b * H + j] + si * tanhf(gg);
    cout[b * H + j] = cv;
    hout[b * H + j] = so * tanhf(cv);
}

// ---------------------------------------------------------------------------
// Linear body. MERGE: k>=K1 operand is the softmax-merged attention context,
// computed on the fly from the two half-L partials (am/az/ar).
// ---------------------------------------------------------------------------
template <bool RELU, bool MERGE>
__device__ void linear_body(int nbase, const float* __restrict__ x1, int K1,
                            const float* __restrict__ Wa, int ldwa,
                            const float* __restrict__ Wb, int ldwb, int Ktot,
                            const float* __restrict__ bias,
                            float* __restrict__ outp, int ldo, int off,
                            float* sm) {
    float (*xs)[132] = (float(*)[132])(sm + SM_XS);
    float (*ws)[128] = (float(*)[128])(sm + SM_WS);
    float* sw = sm + SM_SW;
    int tid = threadIdx.x, b = tid & 63, nq = tid >> 6;

    if (MERGE && tid < 128) {
        int bb = tid >> 1, i = tid & 1;
        float m0 = g_s.am[bb * 2], m1 = g_s.am[bb * 2 + 1];
        float mm = fmaxf(m0, m1);
        float z = expf(m0 - mm) * g_s.az[bb * 2]
                + expf(m1 - mm) * g_s.az[bb * 2 + 1];
        sw[tid] = expf((i ? m1 : m0) - mm) / z;
    }

    int NCH = Ktot >> 7;
    float xr[32], wr[2];
    #pragma unroll
    for (int u = 0; u < 32; u++) {                 // chunk 0: k<128<K1
        int idx = tid + u * 256;
        xr[u] = x1[(idx >> 7) * K1 + (idx & 127)];
    }
    #pragma unroll
    for (int u = 0; u < 2; u++) {
        int idx = tid + u * 256;
        wr[u] = Wa[(nbase + (idx >> 7)) * ldwa + (idx & 127)];
    }

    unsigned long long acc = 0ull;
    for (int ch = 0; ch < NCH; ch++) {
        #pragma unroll
        for (int u = 0; u < 32; u++) {
            int idx = tid + u * 256;
            xs[idx >> 7][idx & 127] = xr[u];
        }
        #pragma unroll
        for (int u = 0; u < 2; u++) {
            int idx = tid + u * 256;
            ws[idx >> 7][idx & 127] = wr[u];
        }
        __syncthreads();
        if (ch + 1 < NCH) {
            int k0 = (ch + 1) * 128;
            #pragma unroll
            for (int u = 0; u < 32; u++) {
                int idx = tid + u * 256, bb = idx >> 7, k = k0 + (idx & 127);
                if (k < K1) xr[u] = x1[bb * K1 + k];
                else if (MERGE) {
                    int k2 = k - K1;
                    xr[u] = sw[bb * 2] * g_s.ar[(bb * 2) * H + k2]
                          + sw[bb * 2 + 1] * g_s.ar[(bb * 2 + 1) * H + k2];
                } else xr[u] = 0.f;
            }
            #pragma unroll
            for (int u = 0; u < 2; u++) {
                int idx = tid + u * 256, rr = idx >> 7, k = k0 + (idx & 127);
                wr[u] = (k < K1) ? Wa[(nbase + rr) * ldwa + k]
                                 : Wb[(nbase + rr) * ldwb + (k - K1)];
            }
        }
        #pragma unroll
        for (int kk = 0; kk < 128; kk += 4) {
            ulonglong2 xv = *(const ulonglong2*)&xs[b][kk];
            ulonglong2 wv = *(const ulonglong2*)&ws[nq][kk];
            fma2(acc, xv.x, wv.x); fma2(acc, xv.y, wv.y);
        }
        __syncthreads();
    }
    int n = nbase + nq;
    float a = red2(acc) + bias[n];
    if (RELU) a = fmaxf(a, 0.f);
    outp[b * ldo + off + n] = a;
}

// ---------------------------------------------------------------------------
// Streamed flash attention: task=(b,half). 512 rows in 16 sub-tiles of 32,
// cp.async double-buffered, online rescale. Writes (m, Z, racc) partials.
// ---------------------------------------------------------------------------
__device__ void attn_body(int task, const float* __restrict__ enc, float* sm) {
    int b = task >> 1, half = task & 1;
    float* buf = sm + SM_ABUF;
    float* s_q = sm + SM_AQ;
    float* s_e = sm + SM_AE;
    float* s_st = sm + SM_AST;
    float* s_p = sm + SM_AP;
    int tid = threadIdx.x, w = tid >> 5, lane = tid & 31;
    const float* base = enc + ((size_t)b * L + (size_t)half * 512) * H;

    if (tid < 128)
        ((float4*)s_q)[tid] = ((const float4*)(g_s.q + b * H))[tid];

    copy_tile_async(buf, base, tid);
    CP_COMMIT();

    float m = -1e30f, Z = 0.f, r0 = 0.f, r1 = 0.f;
    for (int st = 0; st < 16; st++) {
        float* cur = buf + (st & 1) * (32 * 512);
        if (st < 15) {
            copy_tile_async(buf + ((st + 1) & 1) * (32 * 512),
                            base + (st + 1) * 32 * 512, tid);
            CP_COMMIT();
            cp_wait<1>();
        } else {
            cp_wait<0>();
        }
        __syncthreads();
        // e for 4 rows per warp
        #pragma unroll
        for (int rr = 0; rr < 4; rr++) {
            int l = w * 4 + rr;
            float sum = 0.f;
            #pragma unroll
            for (int it = 0; it < 16; it++) {
                int jj = lane + it * 32;
                sum += s_q[jj] * cur[l * 512 + jj];
            }
            #pragma unroll
            for (int o = 16; o > 0; o >>= 1)
                sum += __shfl_xor_sync(0xffffffffu, sum, o);
            if (lane == 0) s_e[l] = sum;
        }
        __syncthreads();
        if (w == 0) {                 // warp 0: tile max, p, psum
            float e = s_e[lane];
            float tmax = e;
            #pragma unroll
            for (int o = 16; o > 0; o >>= 1)
                tmax = fmaxf(tmax, __shfl_xor_sync(0xffffffffu, tmax, o));
            float mn = fmaxf(m, tmax);
            float p = expf(e - mn);
            float ps = p;
            #pragma unroll
            for (int o = 16; o > 0; o >>= 1)
                ps += __shfl_xor_sync(0xffffffffu, ps, o);
            s_p[lane] = p;
            if (lane == 0) { s_st[0] = mn; s_st[1] = ps; }
        }
        __syncthreads();
        float mn = s_st[0];
        float scale = expf(m - mn);
        m = mn;
        Z = Z * scale + s_st[1];
        r0 *= scale; r1 *= scale;
        #pragma unroll 8
        for (int l = 0; l < 32; l++) {
            float p = s_p[l];
            r0 += p * cur[l * 512 + tid];
            r1 += p * cur[l * 512 + tid + 256];
        }
        __syncthreads();
    }
    g_s.ar[(b * 2 + half) * H + tid] = r0;
    g_s.ar[(b * 2 + half) * H + tid + 256] = r1;
    if (tid == 0) { g_s.am[b * 2 + half] = m; g_s.az[b * 2 + half] = Z; }
    __syncthreads();
}

// r[b][:] for next step's ctx fold (4 b per task)
__device__ void rwrite_body(int rw) {
    int tid = threadIdx.x;
    int bb = rw * 4 + (tid >> 6), j0 = tid & 63;
    float m0 = g_s.am[bb * 2], m1 = g_s.am[bb * 2 + 1];
    float mm = fmaxf(m0, m1);
    float z = expf(m0 - mm) * g_s.az[bb * 2]
            + expf(m1 - mm) * g_s.az[bb * 2 + 1];
    float w0 = expf(m0 - mm) / z, w1 = expf(m1 - mm) / z;
    #pragma unroll
    for (int u = 0; u < 8; u++) {
        int j = j0 + u * 64;
        g_s.r[bb * H + j] = w0 * g_s.ar[(bb * 2) * H + j]
                          + w1 * g_s.ar[(bb * 2 + 1) * H + j];
    }
}

// ---------------------------------------------------------------------------
// Persistent decoder: preamble (all precompute) + 128-step loop.
// ---------------------------------------------------------------------------
__global__ void __launch_bounds__(256, 1)
decoder_kernel(int nblk,
               const void* __restrict__ yptr,
               const float* __restrict__ enc,
               const float* __restrict__ emb,
               const float* __restrict__ aWih, const float* __restrict__ aWhh,
               const float* __restrict__ abih, const float* __restrict__ abhh,
               const float* __restrict__ rWih, const float* __restrict__ rWhh,
               const float* __restrict__ rbih, const float* __restrict__ rbhh,
               const float* __restrict__ Wsw, const float* __restrict__ Wsb,
               const float* __restrict__ Whw, const float* __restrict__ Whb,
               const float* __restrict__ W1, const float* __restrict__ b1,
               const float* __restrict__ W2, const float* __restrict__ b2,
               float* __restrict__ out) {
    extern __shared__ __align__(16) float sm[];
    const int bid = blockIdx.x;
    unsigned bk = 0;

    // Preamble: P(256) A2(1024) w1b(256) EW(128) p0(2) cbias(8) b1p(2)
    for (int task = bid; task < 1676; task += nblk) {
        if (task < 256)
            tileP_body((task >> 4) * 32, (task & 15) * 32, Whw, Wsw, sm);
        else if (task < 1280) {
            int u = task - 256;
            tileAB_body(aWih, E + H, E, Whw, H, g_s.A2, H,
                        (u & 15) * 32, (u >> 4) * 32, sm);
        } else if (task < 1536) {
            int u = task - 1280;
            tileAB_body(W1, 2 * H, H, Whw, H, g_s.w1b, H,
                        (u & 15) * 32, (u >> 4) * 32, sm);
        } else if (task < 1664) {
            int u = task - 1536;
            tileEW_body(emb, aWih, abih, abhh, (u & 1) * 32, (u >> 1) * 32, sm);
        } else if (task < 1666) vec_p0(task - 1664, Whw, Wsb);
        else if (task < 1674) vec_cbias(task - 1666, aWih, Whb);
        else vec_b1p(task - 1674, W1, b1, Whb);
    }
    grid_sync(nblk, bk);

    for (int t = 0; t < S; t++) {
        int rp = t & 1, wp = rp ^ 1;

        // S1: att LSTM (x = [r_prev | h0_prev], W = [A2 | aWhh], EW epilogue)
        for (int task = bid; task < 128; task += nblk)
            lstm_body(task * 4, 1, t, yptr, g_s.r, g_s.h0[rp], g_s.c0[rp],
                      g_s.A2, aWhh, nullptr, nullptr,
                      g_s.h0[wp], g_s.c0[wp], sm);
        grid_sync(nblk, bk);

        // S2: rnn layer 0
        for (int task = bid; task < 128; task += nblk)
            lstm_body(task * 4, 0, t, nullptr, g_s.h0[wp], g_s.h1[rp],
                      g_s.c1[rp], rWih, rWhh, rbih, rbhh,
                      g_s.h1[wp], g_s.c1[wp], sm);
        grid_sync(nblk, bk);

        // S3: rnn layer 1
        for (int task = bid; task < 128; task += nblk)
            lstm_body(task * 4, 0, t, nullptr, g_s.h1[wp], g_s.h2[rp],
                      g_s.c2[rp], rWih + 4 * H * H, rWhh + 4 * H * H,
                      rbih + 4 * H, rbhh + 4 * H,
                      g_s.h2[wp], g_s.c2[wp], sm);
        grid_sync(nblk, bk);

        // S4: q = P @ h2 + p0
        for (int task = bid; task < 128; task += nblk)
            linear_body<false, false>(task * 4, g_s.h2[wp], H,
                                      g_s.P, H, nullptr, 0, H,
                                      g_s.p0, g_s.q, H, 0, sm);
        grid_sync(nblk, bk);

        // S5: streamed flash attention (128 tasks: b x half)
        for (int task = bid; task < 128; task += nblk)
            attn_body(task, enc, sm);
        grid_sync(nblk, bk);

        // S6: MLP hidden (merge fused into staging) + r-write tasks
        for (int task = bid; task < 144; task += nblk) {
            if (task < 128)
                linear_body<true, true>(task * 4, g_s.h2[wp], H,
                                        W1, 2 * H, g_s.w1b, H, 2 * H,
                                        g_s.b1p, g_s.hidden, H, 0, sm);
            else
                rwrite_body(task - 128);
        }
        grid_sync(nblk, bk);

        // S7: logits (no barrier: next S1 reads r/h0 only, ordered above)
        for (int task = bid; task < V / 4; task += nblk)
            linear_body<false, false>(task * 4, g_s.hidden, H,
                                      W2, H, nullptr, 0, H,
                                      b2, out, S * V, t * V, sm);
    }
}

// ---------------------------------------------------------------------------
extern "C" void kernel_launch(void* const* d_in, const int* in_sizes, int n_in,
                              void* d_out, int out_size) {
    const void*  y    = d_in[0];
    const float* enc  = (const float*)d_in[1];
    const float* emb  = (const float*)d_in[2];
    const float* aWih = (const float*)d_in[3];
    const float* aWhh = (const float*)d_in[4];
    const float* abih = (const float*)d_in[5];
    const float* abhh = (const float*)d_in[6];
    const float* rWih = (const float*)d_in[7];
    const float* rWhh = (const float*)d_in[8];
    const float* rbih = (const float*)d_in[9];
    const float* rbhh = (const float*)d_in[10];
    const float* Wsw  = (const float*)d_in[11];
    const float* Wsb  = (const float*)d_in[12];
    const float* Whw  = (const float*)d_in[13];
    const float* Whb  = (const float*)d_in[14];
    const float* W1   = (const float*)d_in[15];
    const float* b1   = (const float*)d_in[16];
    const float* W2   = (const float*)d_in[17];
    const float* b2   = (const float*)d_in[18];
    float* out = (float*)d_out;

    const int SMEM_BYTES = SMEM_FLOATS * (int)sizeof(float);  // ~133 KB
    static int configured = -1;
    if (configured < 0) {
        cudaFuncSetAttribute(decoder_kernel,
                             cudaFuncAttributeMaxDynamicSharedMemorySize,
                             SMEM_BYTES);
        configured = 1;
    }

    int dev = 0;
    cudaGetDevice(&dev);
    int sms = 128;
    cudaDeviceGetAttribute(&sms, cudaDevAttrMultiProcessorCount, dev);
    int nblk = sms < 128 ? sms : 128;

    init_kernel<<<(B * H + 255) / 256, 256>>>(y);
    decoder_kernel<<<nblk, 256, SMEM_BYTES>>>(
        nblk, y, enc, emb,
        aWih, aWhh, abih, abhh,
        rWih, rWhh, rbih, rbhh,
        Wsw, Wsb, Whw, Whb, W1, b1, W2, b2, out);
}

// round 10
// speedup vs baseline: 2.1886x; 1.3039x over previous
#include <cuda_runtime.h>
#include <cstdint>

#define B 64
#define S 128
#define L 1024
#define H 512
#define E 256
#define V 64

// ---------------------------------------------------------------------------
struct __align__(256) Scratch {
    float h0[2][B * H], c0[2][B * H];
    float h1[2][B * H], c1[2][B * H];
    float h2[2][B * H], c2[2][B * H];
    float r[B * H];                     // merged attention context (pre-Wh)
    float q[B * H];
    float hidden[B * H];
    float P[H * H], p0[H];              // folded mlp_s/mlp_h query projection
    float A2[4 * H * H], cbias[4 * H];  // ctx fold into att LSTM
    float w1b[H * H], b1p[H];           // ctx fold into MLP
    float EW[V * 4 * H];                // emb @ attWih[:, :E]^T + bih + bhh
    float am[B * 2], az[B * 2];         // per-half softmax stats
    float ar[B * 2 * H];                // per-half unnormalized weighted sums
    int yflag;
};
__device__ Scratch g_s;
// Tree barrier state (monotonic; zeroed by init_kernel each replay)
__device__ unsigned g_grp[8 * 32];      // per-group arrival counter (padded)
__device__ unsigned g_root;
__device__ unsigned g_rel[8 * 32];      // per-group release phase

// Packed f32x2 FMA (sm_100+)
__device__ __forceinline__ void fma2(unsigned long long& a,
                                     unsigned long long x,
                                     unsigned long long w) {
    asm("fma.rn.f32x2 %0, %1, %2, %3;" : "=l"(a) : "l"(x), "l"(w), "l"(a));
}
__device__ __forceinline__ float red2(unsigned long long a) {
    float lo, hi;
    asm("mov.b64 {%0,%1}, %2;" : "=f"(lo), "=f"(hi) : "l"(a));
    return lo + hi;
}

// ---------------------------------------------------------------------------
// Two-level grid barrier: 8 groups; arrivals at group counter, last-in-group
// arrives at root, last-at-root writes 8 release lines; members poll only
// their group's line (16 pollers/line). Requires nblk >= 8.
// ---------------------------------------------------------------------------
__device__ __forceinline__ void grid_sync(int nblk, unsigned& ph) {
    ph++;
    __syncthreads();
    if (threadIdx.x == 0) {
        int g = blockIdx.x & 7;
        unsigned ng = (unsigned)((nblk + 7 - g) >> 3);
        __threadfence();                              // release data writes
        unsigned o = atomicAdd(&g_grp[g * 32], 1u);
        if (o + 1u == ng * ph) {                      // last in group
            __threadfence();
            unsigned ro = atomicAdd(&g_root, 1u);
            if (ro + 1u == 8u * ph) {                 // last group overall
                __threadfence();
                #pragma unroll
                for (int i = 0; i < 8; i++)
                    *((volatile unsigned*)&g_rel[i * 32]) = ph;
            }
        }
        while (*((volatile unsigned*)&g_rel[g * 32]) < ph) { }
        __threadfence();                              // acquire
    }
    __syncthreads();
}

// ---------------------------------------------------------------------------
// cp.async helpers
// ---------------------------------------------------------------------------
__device__ __forceinline__ void cp16(unsigned dst, const float* __restrict__ src) {
    asm volatile("cp.async.cg.shared.global [%0], [%1], 16;"
                 :: "r"(dst), "l"(src));
}
#define CP_COMMIT() asm volatile("cp.async.commit_group;")
template <int N>
__device__ __forceinline__ void cp_wait() {
    asm volatile("cp.async.wait_group %0;" :: "n"(N));
}
// one 32x512 fp32 tile (64KB)
__device__ __forceinline__ void copy_tile_async(float* dst,
                                                const float* __restrict__ src,
                                                int tid) {
    unsigned d = (unsigned)__cvta_generic_to_shared(dst);
    #pragma unroll
    for (int u = 0; u < 16; u++) {
        int fo = (tid + u * 256) * 4;
        cp16(d + fo * 4, src + fo);
    }
}

// Shared-memory views (floats)
#define XS_SZ (64 * 132)
#define SM_XS 0
#define SM_WS2 (2 * XS_SZ)
#define WS_SZ (16 * 128)
#define SM_ABUF 0
#define SM_AQ (2 * 32 * 512)
#define SM_AE (SM_AQ + 512)
#define SM_AST (SM_AE + 32)
#define SM_AP (SM_AST + 4)
#define SMEM_FLOATS (SM_AP + 48)

// ---------------------------------------------------------------------------
__global__ void init_kernel(const void* y) {
    int i = blockIdx.x * blockDim.x + threadIdx.x;
    if (i == 0) {
        g_root = 0u;
        const int* yi = (const int*)y;
        int f = 1;
        for (int k = 0; k < 128; k++)
            if (yi[2 * k + 1] != 0) { f = 0; break; }
        g_s.yflag = f;
    }
    if (i < 8 * 32) { g_grp[i] = 0u; g_rel[i] = 0u; }
    if (i < B * H) {
        g_s.h0[0][i] = 0.f; g_s.c0[0][i] = 0.f;
        g_s.h1[0][i] = 0.f; g_s.c1[0][i] = 0.f;
        g_s.h2[0][i] = 0.f; g_s.c2[0][i] = 0.f;
        g_s.r[i] = 0.f;                 // t=0 ctx contribution is exactly 0
    }
}

// ---------------------------------------------------------------------------
// Preamble tile bodies (32x32 tiles, 256 threads, trailing sync for reuse)
// ---------------------------------------------------------------------------
__device__ void tileP_body(int j0, int k0, const float* __restrict__ Wh,
                           const float* __restrict__ Ws, float* sm) {
    float (*As)[33] = (float(*)[33])sm;
    float (*Bs)[33] = (float(*)[33])(sm + 32 * 33);
    int tid = threadIdx.x, tx = tid & 31, ty = tid >> 5;
    float acc[4] = {0.f, 0.f, 0.f, 0.f};
    for (int i0 = 0; i0 < H; i0 += 32) {
        #pragma unroll
        for (int u = 0; u < 4; u++) {
            int idx = tid + u * 256, ii = idx >> 5, cc = idx & 31;
            As[ii][cc] = Wh[(i0 + ii) * H + j0 + cc];
            Bs[ii][cc] = Ws[(i0 + ii) * H + k0 + cc];
        }
        __syncthreads();
        #pragma unroll
        for (int ii = 0; ii < 32; ii++) {
            float bv = Bs[ii][tx];
            #pragma unroll
            for (int rr = 0; rr < 4; rr++) acc[rr] += As[ii][ty + 8 * rr] * bv;
        }
        __syncthreads();
    }
    #pragma unroll
    for (int rr = 0; rr < 4; rr++)
        g_s.P[(j0 + ty + 8 * rr) * H + k0 + tx] = acc[rr];
    __syncthreads();
}

__device__ void tileAB_body(const float* __restrict__ A, int lda, int offA,
                            const float* __restrict__ Bm, int ldb,
                            float* __restrict__ Cm, int ldc,
                            int n0, int m0, float* sm) {
    float (*As)[33] = (float(*)[33])sm;
    float (*Bs)[33] = (float(*)[33])(sm + 32 * 33);
    int tid = threadIdx.x, tx = tid & 31, ty = tid >> 5;
    float acc[4] = {0.f, 0.f, 0.f, 0.f};
    for (int k0 = 0; k0 < H; k0 += 32) {
        #pragma unroll
        for (int u = 0; u < 4; u++) {
            int idx = tid + u * 256, rr = idx >> 5, cc = idx & 31;
            As[rr][cc] = A[(m0 + rr) * lda + offA + k0 + cc];
            Bs[rr][cc] = Bm[(k0 + rr) * ldb + n0 + cc];
        }
        __syncthreads();
        #pragma unroll
        for (int kk = 0; kk < 32; kk++) {
            float bv = Bs[kk][tx];
            #pragma unroll
            for (int rr = 0; rr < 4; rr++) acc[rr] += As[ty + 8 * rr][kk] * bv;
        }
        __syncthreads();
    }
    #pragma unroll
    for (int rr = 0; rr < 4; rr++)
        Cm[(m0 + ty + 8 * rr) * ldc + n0 + tx] = acc[rr];
    __syncthreads();
}

__device__ void tileEW_body(const float* __restrict__ emb,
                            const float* __restrict__ Wih,
                            const float* __restrict__ bih,
                            const float* __restrict__ bhh,
                            int v0, int j0, float* sm) {
    float (*As)[33] = (float(*)[33])sm;
    float (*Bs)[33] = (float(*)[33])(sm + 32 * 33);
    int tid = threadIdx.x, tx = tid & 31, ty = tid >> 5;
    float acc[4] = {0.f, 0.f, 0.f, 0.f};
    for (int k0 = 0; k0 < E; k0 += 32) {
        #pragma unroll
        for (int u = 0; u < 4; u++) {
            int idx = tid + u * 256, rr = idx >> 5, cc = idx & 31;
            As[rr][cc] = emb[(v0 + rr) * E + k0 + cc];
            Bs[rr][cc] = Wih[(j0 + rr) * (E + H) + k0 + cc];
        }
        __syncthreads();
        #pragma unroll
        for (int kk = 0; kk < 32; kk++) {
            #pragma unroll
            for (int rr = 0; rr < 4; rr++)
                acc[rr] += As[ty + 8 * rr][kk] * Bs[tx][kk];
        }
        __syncthreads();
    }
    #pragma unroll
    for (int rr = 0; rr < 4; rr++) {
        int v = v0 + ty + 8 * rr, j = j0 + tx;
        g_s.EW[v * (4 * H) + j] = acc[rr] + bih[j] + bhh[j];
    }
    __syncthreads();
}

__device__ void vec_p0(int part, const float* __restrict__ Wh,
                       const float* __restrict__ Wsb) {
    int j = part * 256 + threadIdx.x;
    float a = 0.f;
    for (int i = 0; i < H; i++) a += Wh[i * H + j] * Wsb[i];
    g_s.p0[j] = a;
}
__device__ void vec_cbias(int part, const float* __restrict__ Wih,
                          const float* __restrict__ Whb) {
    int j = part * 256 + threadIdx.x;
    float a = 0.f;
    for (int k = 0; k < H; k++) a += Wih[j * (E + H) + E + k] * Whb[k];
    g_s.cbias[j] = a;
}
__device__ void vec_b1p(int part, const float* __restrict__ W1,
                        const float* __restrict__ b1,
                        const float* __restrict__ Whb) {
    int n = part * 256 + threadIdx.x;
    float a = b1[n];
    for (int k = 0; k < H; k++) a += W1[n * 2 * H + H + k] * Whb[k];
    g_s.b1p[n] = a;
}

// ---------------------------------------------------------------------------
// cp.async chunk staging. x rows are B x H (stride H). Chunk ch covers
// k = ch*128..+127, entirely inside [0,H) (lo) or [H,2H) (hi).
// ---------------------------------------------------------------------------
__device__ __forceinline__ void x_issue(float* xsb, int tid, int k0,
                                        const float* __restrict__ xlo,
                                        const float* __restrict__ xhi) {
    const float* xb = (k0 < H) ? xlo + k0 : xhi + (k0 - H);
    unsigned xd = (unsigned)__cvta_generic_to_shared(xsb);
    #pragma unroll
    for (int u = 0; u < 8; u++) {
        int s = tid + u * 256;                // 2048 16B-segs
        int bb = s >> 5, kk4 = (s & 31) * 4;
        cp16(xd + (bb * 132 + kk4) * 4, xb + bb * H + kk4);
    }
}
// LSTM weights: 16 rows (gate*4 + jj), row = gate*H + jbase + jj, stride H
__device__ __forceinline__ void w16_issue(float* wsb, int tid, int k0, int jbase,
                                          const float* __restrict__ Wlo,
                                          const float* __restrict__ Whi) {
    const float* wb = (k0 < H) ? Wlo + k0 : Whi + (k0 - H);
    unsigned wd = (unsigned)__cvta_generic_to_shared(wsb);
    #pragma unroll
    for (int u = 0; u < 2; u++) {
        int s = tid + u * 256;                // 512 segs
        int r16 = s >> 5, kk4 = (s & 31) * 4;
        int row = (r16 >> 2) * H + jbase + (r16 & 3);
        cp16(wd + (r16 * 128 + kk4) * 4, wb + row * H + kk4);
    }
}
// Linear weights: 4 rows nbase+rr with explicit strides
__device__ __forceinline__ void w4_issue(float* wsb, int tid, int k0, int nbase,
                                         int K1,
                                         const float* __restrict__ Wa, int ldwa,
                                         const float* __restrict__ Wb, int ldwb) {
    if (tid < 128) {
        const float* wb; int ld;
        if (k0 < K1) { wb = Wa + (size_t)nbase * ldwa + k0; ld = ldwa; }
        else         { wb = Wb + (size_t)nbase * ldwb + (k0 - K1); ld = ldwb; }
        int rr = tid >> 5, kk4 = (tid & 31) * 4;
        unsigned wd = (unsigned)__cvta_generic_to_shared(wsb);
        cp16(wd + (rr * 128 + kk4) * 4, wb + rr * ld + kk4);
    }
}

// ---------------------------------------------------------------------------
// LSTM body, K=1024: x=[xlo|hprev], W=[Wlo|Whh], cp.async double-buffered.
// first: epilogue adds EW[y] (+cbias for t>0) instead of bih+bhh.
// ---------------------------------------------------------------------------
__device__ void lstm_body(int jbase, int first, int t,
                          const void* __restrict__ yptr,
                          const float* __restrict__ xlo,
                          const float* __restrict__ hprev,
                          const float* __restrict__ cprev,
                          const float* __restrict__ Wlo,
                          const float* __restrict__ Whh,
                          const float* __restrict__ bih,
                          const float* __restrict__ bhh,
                          float* __restrict__ hout,
                          float* __restrict__ cout, float* sm) {
    int tid = threadIdx.x, b = tid & 63, jq = tid >> 6;

    x_issue(sm + SM_XS, tid, 0, xlo, hprev);
    w16_issue(sm + SM_WS2, tid, 0, jbase, Wlo, Whh);
    CP_COMMIT();

    unsigned long long a0 = 0ull, a1 = 0ull, a2 = 0ull, a3 = 0ull;
    #pragma unroll 1
    for (int ch = 0; ch < 8; ch++) {
        if (ch < 7) {
            int nb = (ch + 1) & 1;
            x_issue(sm + SM_XS + nb * XS_SZ, tid, (ch + 1) * 128, xlo, hprev);
            w16_issue(sm + SM_WS2 + nb * WS_SZ, tid, (ch + 1) * 128, jbase,
                      Wlo, Whh);
            CP_COMMIT();
            cp_wait<1>();
        } else {
            cp_wait<0>();
        }
        __syncthreads();
        const float* xs = sm + SM_XS + (ch & 1) * XS_SZ + b * 132;
        const float* ws = sm + SM_WS2 + (ch & 1) * WS_SZ;
        #pragma unroll
        for (int kk = 0; kk < 128; kk += 4) {
            ulonglong2 xv = *(const ulonglong2*)(xs + kk);
            ulonglong2 w0 = *(const ulonglong2*)(ws + jq * 128 + kk);
            ulonglong2 w1 = *(const ulonglong2*)(ws + (4 + jq) * 128 + kk);
            ulonglong2 w2 = *(const ulonglong2*)(ws + (8 + jq) * 128 + kk);
            ulonglong2 w3 = *(const ulonglong2*)(ws + (12 + jq) * 128 + kk);
            fma2(a0, xv.x, w0.x); fma2(a0, xv.y, w0.y);
            fma2(a1, xv.x, w1.x); fma2(a1, xv.y, w1.y);
            fma2(a2, xv.x, w2.x); fma2(a2, xv.y, w2.y);
            fma2(a3, xv.x, w3.x); fma2(a3, xv.y, w3.y);
        }
        __syncthreads();
    }

    int j = jbase + jq;
    float gi = red2(a0), gf = red2(a1), gg = red2(a2), go = red2(a3);
    if (first) {
        int yy = g_s.yflag ? (int)((const long long*)yptr)[b * S + t]
                           : ((const int*)yptr)[b * S + t];
        const float* ew = g_s.EW + yy * (4 * H);
        gi += ew[j];         gf += ew[j + H];
        gg += ew[j + 2 * H]; go += ew[j + 3 * H];
        if (t > 0) {
            gi += g_s.cbias[j];         gf += g_s.cbias[j + H];
            gg += g_s.cbias[j + 2 * H]; go += g_s.cbias[j + 3 * H];
        }
    } else {
        gi += bih[j] + bhh[j];
        gf += bih[j + H] + bhh[j + H];
        gg += bih[j + 2 * H] + bhh[j + 2 * H];
        go += bih[j + 3 * H] + bhh[j + 3 * H];
    }
    float si = 1.f / (1.f + expf(-gi));
    float sf = 1.f / (1.f + expf(-gf));
    float so = 1.f / (1.f + expf(-go));
    float cv = sf * cprev[b * H + j] + si * tanhf(gg);
    cout[b * H + j] = cv;
    hout[b * H + j] = so * tanhf(cv);
}

// ---------------------------------------------------------------------------
// Linear body: out[b,n] = act(bias[n] + sum_{k<K1} x1[b,k] Wa[n,k]
//                                     + sum_k x2[b,k] Wb[n,k])
// All-plain sources, cp.async double-buffered. K1, Ktot multiples of 128.
// ---------------------------------------------------------------------------
template <bool RELU>
__device__ void linear_body(int nbase, const float* __restrict__ x1, int K1,
                            const float* __restrict__ x2,
                            const float* __restrict__ Wa, int ldwa,
                            const float* __restrict__ Wb, int ldwb, int Ktot,
                            const float* __restrict__ bias,
                            float* __restrict__ outp, int ldo, int off,
                            float* sm) {
    int tid = threadIdx.x, b = tid & 63, nq = tid >> 6;
    int NCH = Ktot >> 7;

    x_issue(sm + SM_XS, tid, 0, x1, x2);   // K1 == H for split inputs
    w4_issue(sm + SM_WS2, tid, 0, nbase, K1, Wa, ldwa, Wb, ldwb);
    CP_COMMIT();

    unsigned long long acc = 0ull;
    #pragma unroll 1
    for (int ch = 0; ch < NCH; ch++) {
        if (ch + 1 < NCH) {
            int nb = (ch + 1) & 1;
            x_issue(sm + SM_XS + nb * XS_SZ, tid, (ch + 1) * 128, x1, x2);
            w4_issue(sm + SM_WS2 + nb * WS_SZ, tid, (ch + 1) * 128, nbase, K1,
                     Wa, ldwa, Wb, ldwb);
            CP_COMMIT();
            cp_wait<1>();
        } else {
            cp_wait<0>();
        }
        __syncthreads();
        const float* xs = sm + SM_XS + (ch & 1) * XS_SZ + b * 132;
        const float* ws = sm + SM_WS2 + (ch & 1) * WS_SZ + nq * 128;
        #pragma unroll
        for (int kk = 0; kk < 128; kk += 4) {
            ulonglong2 xv = *(const ulonglong2*)(xs + kk);
            ulonglong2 wv = *(const ulonglong2*)(ws + kk);
            fma2(acc, xv.x, wv.x); fma2(acc, xv.y, wv.y);
        }
        __syncthreads();
    }
    int n = nbase + nq;
    float a = red2(acc) + bias[n];
    if (RELU) a = fmaxf(a, 0.f);
    outp[b * ldo + off + n] = a;
}

// ---------------------------------------------------------------------------
// Streamed flash attention: task=(b,half), 16 sub-tiles of 32x512, cp.async
// double-buffered, online rescale -> (m, Z, racc) partials.
// ---------------------------------------------------------------------------
__device__ void attn_body(int task, const float* __restrict__ enc, float* sm) {
    int b = task >> 1, half = task & 1;
    float* buf = sm + SM_ABUF;
    float* s_q = sm + SM_AQ;
    float* s_e = sm + SM_AE;
    float* s_st = sm + SM_AST;
    float* s_p = sm + SM_AP;
    int tid = threadIdx.x, w = tid >> 5, lane = tid & 31;
    const float* base = enc + ((size_t)b * L + (size_t)half * 512) * H;

    if (tid < 128)
        ((float4*)s_q)[tid] = ((const float4*)(g_s.q + b * H))[tid];

    copy_tile_async(buf, base, tid);
    CP_COMMIT();

    float m = -1e30f, Z = 0.f, r0 = 0.f, r1 = 0.f;
    #pragma unroll 1
    for (int st = 0; st < 16; st++) {
        float* cur = buf + (st & 1) * (32 * 512);
        if (st < 15) {
            copy_tile_async(buf + ((st + 1) & 1) * (32 * 512),
                            base + (st + 1) * 32 * 512, tid);
            CP_COMMIT();
            cp_wait<1>();
        } else {
            cp_wait<0>();
        }
        __syncthreads();
        #pragma unroll
        for (int rr = 0; rr < 4; rr++) {
            int l = w * 4 + rr;
            float sum = 0.f;
            #pragma unroll
            for (int it = 0; it < 16; it++) {
                int jj = lane + it * 32;
                sum += s_q[jj] * cur[l * 512 + jj];
            }
            #pragma unroll
            for (int o = 16; o > 0; o >>= 1)
                sum += __shfl_xor_sync(0xffffffffu, sum, o);
            if (lane == 0) s_e[l] = sum;
        }
        __syncthreads();
        if (w == 0) {
            float e = s_e[lane];
            float tmax = e;
            #pragma unroll
            for (int o = 16; o > 0; o >>= 1)
                tmax = fmaxf(tmax, __shfl_xor_sync(0xffffffffu, tmax, o));
            float mn = fmaxf(m, tmax);
            float p = expf(e - mn);
            float ps = p;
            #pragma unroll
            for (int o = 16; o > 0; o >>= 1)
                ps += __shfl_xor_sync(0xffffffffu, ps, o);
            s_p[lane] = p;
            if (lane == 0) { s_st[0] = mn; s_st[1] = ps; }
        }
        __syncthreads();
        float mn = s_st[0];
        float scale = expf(m - mn);
        m = mn;
        Z = Z * scale + s_st[1];
        r0 *= scale; r1 *= scale;
        #pragma unroll 8
        for (int l = 0; l < 32; l++) {
            float p = s_p[l];
            r0 += p * cur[l * 512 + tid];
            r1 += p * cur[l * 512 + tid + 256];
        }
        __syncthreads();
    }
    g_s.ar[(b * 2 + half) * H + tid] = r0;
    g_s.ar[(b * 2 + half) * H + tid + 256] = r1;
    if (tid == 0) { g_s.am[b * 2 + half] = m; g_s.az[b * 2 + half] = Z; }
    __syncthreads();
}

// Distributed r-merge: task=(b, j-half); one element per thread.
__device__ void rwrite_body(int task) {
    int bb = task >> 1, j = ((task & 1) << 8) + threadIdx.x;
    float m0 = g_s.am[bb * 2], m1 = g_s.am[bb * 2 + 1];
    float mm = fmaxf(m0, m1);
    float z = expf(m0 - mm) * g_s.az[bb * 2]
            + expf(m1 - mm) * g_s.az[bb * 2 + 1];
    float w0 = expf(m0 - mm) / z, w1 = expf(m1 - mm) / z;
    g_s.r[bb * H + j] = w0 * g_s.ar[(bb * 2) * H + j]
                      + w1 * g_s.ar[(bb * 2 + 1) * H + j];
}

// ---------------------------------------------------------------------------
// Persistent decoder: preamble + 128-step loop, 7 tree-barriers/step.
// ---------------------------------------------------------------------------
__global__ void __launch_bounds__(256, 1)
decoder_kernel(int nblk,
               const void* __restrict__ yptr,
               const float* __restrict__ enc,
               const float* __restrict__ emb,
               const float* __restrict__ aWih, const float* __restrict__ aWhh,
               const float* __restrict__ abih, const float* __restrict__ abhh,
               const float* __restrict__ rWih, const float* __restrict__ rWhh,
               const float* __restrict__ rbih, const float* __restrict__ rbhh,
               const float* __restrict__ Wsw, const float* __restrict__ Wsb,
               const float* __restrict__ Whw, const float* __restrict__ Whb,
               const float* __restrict__ W1, const float* __restrict__ b1,
               const float* __restrict__ W2, const float* __restrict__ b2,
               float* __restrict__ out) {
    extern __shared__ __align__(16) float sm[];
    const int bid = blockIdx.x;
    unsigned ph = 0;

    // Preamble: P(256) A2(1024) w1b(256) EW(128) p0(2) cbias(8) b1p(2)
    for (int task = bid; task < 1676; task += nblk) {
        if (task < 256)
            tileP_body((task >> 4) * 32, (task & 15) * 32, Whw, Wsw, sm);
        else if (task < 1280) {
            int u = task - 256;
            tileAB_body(aWih, E + H, E, Whw, H, g_s.A2, H,
                        (u & 15) * 32, (u >> 4) * 32, sm);
        } else if (task < 1536) {
            int u = task - 1280;
            tileAB_body(W1, 2 * H, H, Whw, H, g_s.w1b, H,
                        (u & 15) * 32, (u >> 4) * 32, sm);
        } else if (task < 1664) {
            int u = task - 1536;
            tileEW_body(emb, aWih, abih, abhh, (u & 1) * 32, (u >> 1) * 32, sm);
        } else if (task < 1666) vec_p0(task - 1664, Whw, Wsb);
        else if (task < 1674) vec_cbias(task - 1666, aWih, Whb);
        else vec_b1p(task - 1674, W1, b1, Whb);
    }
    grid_sync(nblk, ph);

    for (int t = 0; t < S; t++) {
        int rp = t & 1, wp = rp ^ 1;

        // S1: att LSTM (x = [r_prev | h0_prev], W = [A2 | aWhh], EW epilogue)
        for (int task = bid; task < 128; task += nblk)
            lstm_body(task * 4, 1, t, yptr, g_s.r, g_s.h0[rp], g_s.c0[rp],
                      g_s.A2, aWhh, nullptr, nullptr,
                      g_s.h0[wp], g_s.c0[wp], sm);
        grid_sync(nblk, ph);

        // S2: rnn layer 0
        for (int task = bid; task < 128; task += nblk)
            lstm_body(task * 4, 0, t, nullptr, g_s.h0[wp], g_s.h1[rp],
                      g_s.c1[rp], rWih, rWhh, rbih, rbhh,
                      g_s.h1[wp], g_s.c1[wp], sm);
        grid_sync(nblk, ph);

        // S3: rnn layer 1
        for (int task = bid; task < 128; task += nblk)
            lstm_body(task * 4, 0, t, nullptr, g_s.h1[wp], g_s.h2[rp],
                      g_s.c2[rp], rWih + 4 * H * H, rWhh + 4 * H * H,
                      rbih + 4 * H, rbhh + 4 * H,
                      g_s.h2[wp], g_s.c2[wp], sm);
        grid_sync(nblk, ph);

        // S4: q = P @ h2 + p0
        for (int task = bid; task < 128; task += nblk)
            linear_body<false>(task * 4, g_s.h2[wp], H, nullptr,
                               g_s.P, H, nullptr, 0, H,
                               g_s.p0, g_s.q, H, 0, sm);
        grid_sync(nblk, ph);

        // S5: streamed flash attention (128 tasks: b x half)
        for (int task = bid; task < 128; task += nblk)
            attn_body(task, enc, sm);
        grid_sync(nblk, ph);

        // S6: distributed softmax merge -> r (128 tiny tasks)
        for (int task = bid; task < 128; task += nblk)
            rwrite_body(task);
        grid_sync(nblk, ph);

        // S7: hidden = relu(W1a@h2 + w1b@r + b1')
        for (int task = bid; task < 128; task += nblk)
            linear_body<true>(task * 4, g_s.h2[wp], H, g_s.r,
                              W1, 2 * H, g_s.w1b, H, 2 * H,
                              g_s.b1p, g_s.hidden, H, 0, sm);
        grid_sync(nblk, ph);

        // S8: logits (16 tasks; no barrier — next S1 is hazard-free)
        for (int task = bid; task < V / 4; task += nblk)
            linear_body<false>(task * 4, g_s.hidden, H, nullptr,
                               W2, H, nullptr, 0, H,
                               b2, out, S * V, t * V, sm);
    }
}

// ---------------------------------------------------------------------------
extern "C" void kernel_launch(void* const* d_in, const int* in_sizes, int n_in,
                              void* d_out, int out_size) {
    const void*  y    = d_in[0];
    const float* enc  = (const float*)d_in[1];
    const float* emb  = (const float*)d_in[2];
    const float* aWih = (const float*)d_in[3];
    const float* aWhh = (const float*)d_in[4];
    const float* abih = (const float*)d_in[5];
    const float* abhh = (const float*)d_in[6];
    const float* rWih = (const float*)d_in[7];
    const float* rWhh = (const float*)d_in[8];
    const float* rbih = (const float*)d_in[9];
    const float* rbhh = (const float*)d_in[10];
    const float* Wsw  = (const float*)d_in[11];
    const float* Wsb  = (const float*)d_in[12];
    const float* Whw  = (const float*)d_in[13];
    const float* Whb  = (const float*)d_in[14];
    const float* W1   = (const float*)d_in[15];
    const float* b1   = (const float*)d_in[16];
    const float* W2   = (const float*)d_in[17];
    const float* b2   = (const float*)d_in[18];
    float* out = (float*)d_out;

    const int SMEM_BYTES = SMEM_FLOATS * (int)sizeof(float);  // ~133 KB
    static int configured = -1;
    if (configured < 0) {
        cudaFuncSetAttribute(decoder_kernel,
                             cudaFuncAttributeMaxDynamicSharedMemorySize,
                             SMEM_BYTES);
        configured = 1;
    }

    int dev = 0;
    cudaGetDevice(&dev);
    int sms = 128;
    cudaDeviceGetAttribute(&sms, cudaDevAttrMultiProcessorCount, dev);
    int nblk = sms < 128 ? sms : 128;

    init_kernel<<<(B * H + 255) / 256, 256>>>(y);
    decoder_kernel<<<nblk, 256, SMEM_BYTES>>>(
        nblk, y, enc, emb,
        aWih, aWhh, abih, abhh,
        rWih, rWhh, rbih, rbhh,
        Wsw, Wsb, Whw, Whb, W1, b1, W2, b2, out);
}

// round 14
// speedup vs baseline: 2.3757x; 1.0855x over previous
#include <cuda_runtime.h>
#include <cstdint>

#define B 64
#define S 128
#define L 1024
#define H 512
#define E 256
#define V 64

struct __align__(256) Scratch {
    float h0[2][B * H], c0[2][B * H];
    float h1[2][B * H], c1[2][B * H];
    float h2[2][B * H], c2[2][B * H];
    float r[B * H];
    float q[B * H];
    float hidden[B * H];
    float P[H * H], p0[H];
    float A2[4 * H * H], cbias[4 * H];
    float w1b[H * H], b1p[H];
    float EW[V * 4 * H];
    float am[B * 2], az[B * 2];
    float ar[B * 2 * H];
    int yflag;
};
__device__ Scratch g_s;
__device__ unsigned g_grp[8 * 32];
__device__ unsigned g_root;
__device__ unsigned g_rel[8 * 32];

__device__ __forceinline__ void fma2(unsigned long long& a,
                                     unsigned long long x,
                                     unsigned long long w) {
    asm("fma.rn.f32x2 %0, %1, %2, %3;" : "=l"(a) : "l"(x), "l"(w), "l"(a));
}
__device__ __forceinline__ float red2(unsigned long long a) {
    float lo, hi;
    asm("mov.b64 {%0,%1}, %2;" : "=f"(lo), "=f"(hi) : "l"(a));
    return lo + hi;
}

// Two-level grid barrier (R10-proven: full fences). nblk >= 8.
__device__ __forceinline__ void grid_sync(int nblk, unsigned& ph) {
    ph++;
    __syncthreads();
    if (threadIdx.x == 0) {
        int g = blockIdx.x & 7;
        unsigned ng = (unsigned)((nblk + 7 - g) >> 3);
        __threadfence();
        unsigned o = atomicAdd(&g_grp[g * 32], 1u);
        if (o + 1u == ng * ph) {
            __threadfence();
            unsigned ro = atomicAdd(&g_root, 1u);
            if (ro + 1u == 8u * ph) {
                __threadfence();
                #pragma unroll
                for (int i = 0; i < 8; i++)
                    *((volatile unsigned*)&g_rel[i * 32]) = ph;
            }
        }
        while (*((volatile unsigned*)&g_rel[g * 32]) < ph) { }
        __threadfence();
    }
    __syncthreads();
}

__device__ __forceinline__ void cp16(unsigned dst, const float* __restrict__ src) {
    asm volatile("cp.async.cg.shared.global [%0], [%1], 16;"
                 :: "r"(dst), "l"(src));
}
#define CP_COMMIT() asm volatile("cp.async.commit_group;")
template <int N>
__device__ __forceinline__ void cp_wait() {
    asm volatile("cp.async.wait_group %0;" :: "n"(N));
}
__device__ __forceinline__ void copy_tile_async(float* dst,
                                                const float* __restrict__ src,
                                                int tid) {
    unsigned d = (unsigned)__cvta_generic_to_shared(dst);
    #pragma unroll
    for (int u = 0; u < 16; u++) {
        int fo = (tid + u * 256) * 4;
        cp16(d + fo * 4, src + fo);
    }
}

#define XS_SZ (64 * 132)
#define SM_XS 0
#define SM_WS2 (2 * XS_SZ)
#define WS_SZ (16 * 128)
#define SM_ABUF 0
#define SMEM_FLOATS (2 * 32 * 512 + 32)

__global__ void init_kernel(const void* y) {
    int i = blockIdx.x * blockDim.x + threadIdx.x;
    if (i == 0) {
        g_root = 0u;
        const int* yi = (const int*)y;
        int f = 1;
        for (int k = 0; k < 128; k++)
            if (yi[2 * k + 1] != 0) { f = 0; break; }
        g_s.yflag = f;
    }
    if (i < 8 * 32) { g_grp[i] = 0u; g_rel[i] = 0u; }
    if (i < B * H) {
        g_s.h0[0][i] = 0.f; g_s.c0[0][i] = 0.f;
        g_s.h1[0][i] = 0.f; g_s.c1[0][i] = 0.f;
        g_s.h2[0][i] = 0.f; g_s.c2[0][i] = 0.f;
        g_s.r[i] = 0.f;
    }
}

// ---- preamble tile bodies (32x32, 256 thr) --------------------------------
__device__ void tileP_body(int j0, int k0, const float* __restrict__ Wh,
                           const float* __restrict__ Ws, float* sm) {
    float (*As)[33] = (float(*)[33])sm;
    float (*Bs)[33] = (float(*)[33])(sm + 32 * 33);
    int tid = threadIdx.x, tx = tid & 31, ty = tid >> 5;
    float acc[4] = {0.f, 0.f, 0.f, 0.f};
    for (int i0 = 0; i0 < H; i0 += 32) {
        #pragma unroll
        for (int u = 0; u < 4; u++) {
            int idx = tid + u * 256, ii = idx >> 5, cc = idx & 31;
            As[ii][cc] = Wh[(i0 + ii) * H + j0 + cc];
            Bs[ii][cc] = Ws[(i0 + ii) * H + k0 + cc];
        }
        __syncthreads();
        #pragma unroll
        for (int ii = 0; ii < 32; ii++) {
            float bv = Bs[ii][tx];
            #pragma unroll
            for (int rr = 0; rr < 4; rr++) acc[rr] += As[ii][ty + 8 * rr] * bv;
        }
        __syncthreads();
    }
    #pragma unroll
    for (int rr = 0; rr < 4; rr++)
        g_s.P[(j0 + ty + 8 * rr) * H + k0 + tx] = acc[rr];
    __syncthreads();
}

__device__ void tileAB_body(const float* __restrict__ A, int lda, int offA,
                            const float* __restrict__ Bm, int ldb,
                            float* __restrict__ Cm, int ldc,
                            int n0, int m0, float* sm) {
    float (*As)[33] = (float(*)[33])sm;
    float (*Bs)[33] = (float(*)[33])(sm + 32 * 33);
    int tid = threadIdx.x, tx = tid & 31, ty = tid >> 5;
    float acc[4] = {0.f, 0.f, 0.f, 0.f};
    for (int k0 = 0; k0 < H; k0 += 32) {
        #pragma unroll
        for (int u = 0; u < 4; u++) {
            int idx = tid + u * 256, rr = idx >> 5, cc = idx & 31;
            As[rr][cc] = A[(m0 + rr) * lda + offA + k0 + cc];
            Bs[rr][cc] = Bm[(k0 + rr) * ldb + n0 + cc];
        }
        __syncthreads();
        #pragma unroll
        for (int kk = 0; kk < 32; kk++) {
            float bv = Bs[kk][tx];
            #pragma unroll
            for (int rr = 0; rr < 4; rr++) acc[rr] += As[ty + 8 * rr][kk] * bv;
        }
        __syncthreads();
    }
    #pragma unroll
    for (int rr = 0; rr < 4; rr++)
        Cm[(m0 + ty + 8 * rr) * ldc + n0 + tx] = acc[rr];
    __syncthreads();
}

__device__ void tileEW_body(const float* __restrict__ emb,
                            const float* __restrict__ Wih,
                            const float* __restrict__ bih,
                            const float* __restrict__ bhh,
                            int v0, int j0, float* sm) {
    float (*As)[33] = (float(*)[33])sm;
    float (*Bs)[33] = (float(*)[33])(sm + 32 * 33);
    int tid = threadIdx.x, tx = tid & 31, ty = tid >> 5;
    float acc[4] = {0.f, 0.f, 0.f, 0.f};
    for (int k0 = 0; k0 < E; k0 += 32) {
        #pragma unroll
        for (int u = 0; u < 4; u++) {
            int idx = tid + u * 256, rr = idx >> 5, cc = idx & 31;
            As[rr][cc] = emb[(v0 + rr) * E + k0 + cc];
            Bs[rr][cc] = Wih[(j0 + rr) * (E + H) + k0 + cc];
        }
        __syncthreads();
        #pragma unroll
        for (int kk = 0; kk < 32; kk++) {
            #pragma unroll
            for (int rr = 0; rr < 4; rr++)
                acc[rr] += As[ty + 8 * rr][kk] * Bs[tx][kk];
        }
        __syncthreads();
    }
    #pragma unroll
    for (int rr = 0; rr < 4; rr++) {
        int v = v0 + ty + 8 * rr, j = j0 + tx;
        g_s.EW[v * (4 * H) + j] = acc[rr] + bih[j] + bhh[j];
    }
    __syncthreads();
}

__device__ void vec_p0(int part, const float* __restrict__ Wh,
                       const float* __restrict__ Wsb) {
    int j = part * 256 + threadIdx.x;
    float a = 0.f;
    for (int i = 0; i < H; i++) a += Wh[i * H + j] * Wsb[i];
    g_s.p0[j] = a;
}
__device__ void vec_cbias(int part, const float* __restrict__ Wih,
                          const float* __restrict__ Whb) {
    int j = part * 256 + threadIdx.x;
    float a = 0.f;
    for (int k = 0; k < H; k++) a += Wih[j * (E + H) + E + k] * Whb[k];
    g_s.cbias[j] = a;
}
__device__ void vec_b1p(int part, const float* __restrict__ W1,
                        const float* __restrict__ b1,
                        const float* __restrict__ Whb) {
    int n = part * 256 + threadIdx.x;
    float a = b1[n];
    for (int k = 0; k < H; k++) a += W1[n * 2 * H + H + k] * Whb[k];
    g_s.b1p[n] = a;
}

// ---- cp.async chunk staging ----------------------------------------------
__device__ __forceinline__ void x_issue(float* xsb, int tid, int k0,
                                        const float* __restrict__ xlo,
                                        const float* __restrict__ xhi) {
    const float* xb = (k0 < H) ? xlo + k0 : xhi + (k0 - H);
    unsigned xd = (unsigned)__cvta_generic_to_shared(xsb);
    #pragma unroll
    for (int u = 0; u < 8; u++) {
        int s = tid + u * 256;
        int bb = s >> 5, kk4 = (s & 31) * 4;
        cp16(xd + (bb * 132 + kk4) * 4, xb + bb * H + kk4);
    }
}
__device__ __forceinline__ void w16_issue(float* wsb, int tid, int k0, int jbase,
                                          const float* __restrict__ Wlo,
                                          const float* __restrict__ Whi) {
    const float* wb = (k0 < H) ? Wlo + k0 : Whi + (k0 - H);
    unsigned wd = (unsigned)__cvta_generic_to_shared(wsb);
    #pragma unroll
    for (int u = 0; u < 2; u++) {
        int s = tid + u * 256;
        int r16 = s >> 5, kk4 = (s & 31) * 4;
        int row = (r16 >> 2) * H + jbase + (r16 & 3);
        cp16(wd + (r16 * 128 + kk4) * 4, wb + row * H + kk4);
    }
}
__device__ __forceinline__ void w4_issue(float* wsb, int tid, int k0, int nbase,
                                         int K1,
                                         const float* __restrict__ Wa, int ldwa,
                                         const float* __restrict__ Wb, int ldwb) {
    if (tid < 128) {
        const float* wb; int ld;
        if (k0 < K1) { wb = Wa + (size_t)nbase * ldwa + k0; ld = ldwa; }
        else         { wb = Wb + (size_t)nbase * ldwb + (k0 - K1); ld = ldwb; }
        int rr = tid >> 5, kk4 = (tid & 31) * 4;
        unsigned wd = (unsigned)__cvta_generic_to_shared(wsb);
        cp16(wd + (rr * 128 + kk4) * 4, wb + rr * ld + kk4);
    }
}

// ---- LSTM body, K=1024 ----------------------------------------------------
__device__ void lstm_body(int jbase, int first, int t,
                          const void* __restrict__ yptr,
                          const float* __restrict__ xlo,
                          const float* __restrict__ hprev,
                          const float* __restrict__ cprev,
                          const float* __restrict__ Wlo,
                          const float* __restrict__ Whh,
                          const float* __restrict__ bih,
                          const float* __restrict__ bhh,
                          float* __restrict__ hout,
                          float* __restrict__ cout, float* sm) {
    int tid = threadIdx.x, b = tid & 63, jq = tid >> 6;

    x_issue(sm + SM_XS, tid, 0, xlo, hprev);
    w16_issue(sm + SM_WS2, tid, 0, jbase, Wlo, Whh);
    CP_COMMIT();

    unsigned long long a0 = 0ull, a1 = 0ull, a2 = 0ull, a3 = 0ull;
    #pragma unroll 1
    for (int ch = 0; ch < 8; ch++) {
        if (ch < 7) {
            int nb = (ch + 1) & 1;
            x_issue(sm + SM_XS + nb * XS_SZ, tid, (ch + 1) * 128, xlo, hprev);
            w16_issue(sm + SM_WS2 + nb * WS_SZ, tid, (ch + 1) * 128, jbase,
                      Wlo, Whh);
            CP_COMMIT();
            cp_wait<1>();
        } else {
            cp_wait<0>();
        }
        __syncthreads();
        const float* xs = sm + SM_XS + (ch & 1) * XS_SZ + b * 132;
        const float* ws = sm + SM_WS2 + (ch & 1) * WS_SZ;
        #pragma unroll
        for (int kk = 0; kk < 128; kk += 4) {
            ulonglong2 xv = *(const ulonglong2*)(xs + kk);
            ulonglong2 w0 = *(const ulonglong2*)(ws + jq * 128 + kk);
            ulonglong2 w1 = *(const ulonglong2*)(ws + (4 + jq) * 128 + kk);
            ulonglong2 w2 = *(const ulonglong2*)(ws + (8 + jq) * 128 + kk);
            ulonglong2 w3 = *(const ulonglong2*)(ws + (12 + jq) * 128 + kk);
            fma2(a0, xv.x, w0.x); fma2(a0, xv.y, w0.y);
            fma2(a1, xv.x, w1.x); fma2(a1, xv.y, w1.y);
            fma2(a2, xv.x, w2.x); fma2(a2, xv.y, w2.y);
            fma2(a3, xv.x, w3.x); fma2(a3, xv.y, w3.y);
        }
        __syncthreads();
    }

    int j = jbase + jq;
    float gi = red2(a0), gf = red2(a1), gg = red2(a2), go = red2(a3);
    if (first) {
        int yy = g_s.yflag ? (int)((const long long*)yptr)[b * S + t]
                           : ((const int*)yptr)[b * S + t];
        const float* ew = g_s.EW + yy * (4 * H);
        gi += ew[j];         gf += ew[j + H];
        gg += ew[j + 2 * H]; go += ew[j + 3 * H];
        if (t > 0) {
            gi += g_s.cbias[j];         gf += g_s.cbias[j + H];
            gg += g_s.cbias[j + 2 * H]; go += g_s.cbias[j + 3 * H];
        }
    } else {
        gi += bih[j] + bhh[j];
        gf += bih[j + H] + bhh[j + H];
        gg += bih[j + 2 * H] + bhh[j + 2 * H];
        go += bih[j + 3 * H] + bhh[j + 3 * H];
    }
    float si = 1.f / (1.f + expf(-gi));
    float sf = 1.f / (1.f + expf(-gf));
    float so = 1.f / (1.f + expf(-go));
    float cv = sf * cprev[b * H + j] + si * tanhf(gg);
    cout[b * H + j] = cv;
    hout[b * H + j] = so * tanhf(cv);
}

// ---- Linear body ----------------------------------------------------------
template <bool RELU>
__device__ void linear_body(int nbase, const float* __restrict__ x1, int K1,
                            const float* __restrict__ x2,
                            const float* __restrict__ Wa, int ldwa,
                            const float* __restrict__ Wb, int ldwb, int Ktot,
                            const float* __restrict__ bias,
                            float* __restrict__ outp, int ldo, int off,
                            float* sm) {
    int tid = threadIdx.x, b = tid & 63, nq = tid >> 6;
    int NCH = Ktot >> 7;

    x_issue(sm + SM_XS, tid, 0, x1, x2);
    w4_issue(sm + SM_WS2, tid, 0, nbase, K1, Wa, ldwa, Wb, ldwb);
    CP_COMMIT();

    unsigned long long acc = 0ull;
    #pragma unroll 1
    for (int ch = 0; ch < NCH; ch++) {
        if (ch + 1 < NCH) {
            int nb = (ch + 1) & 1;
            x_issue(sm + SM_XS + nb * XS_SZ, tid, (ch + 1) * 128, x1, x2);
            w4_issue(sm + SM_WS2 + nb * WS_SZ, tid, (ch + 1) * 128, nbase, K1,
                     Wa, ldwa, Wb, ldwb);
            CP_COMMIT();
            cp_wait<1>();
        } else {
            cp_wait<0>();
        }
        __syncthreads();
        const float* xs = sm + SM_XS + (ch & 1) * XS_SZ + b * 132;
        const float* ws = sm + SM_WS2 + (ch & 1) * WS_SZ + nq * 128;
        #pragma unroll
        for (int kk = 0; kk < 128; kk += 4) {
            ulonglong2 xv = *(const ulonglong2*)(xs + kk);
            ulonglong2 wv = *(const ulonglong2*)(ws + kk);
            fma2(acc, xv.x, wv.x); fma2(acc, xv.y, wv.y);
        }
        __syncthreads();
    }
    int n = nbase + nq;
    float a = red2(acc) + bias[n];
    if (RELU) a = fmaxf(a, 0.f);
    outp[b * ldo + off + n] = a;
}

// ---- Per-warp online-softmax flash attention ------------------------------
// task=(b,half): 512 rows in 16 tiles of 32. Each warp owns 4 rows/tile,
// per-warp (m,Z,racc[16]) in registers. Two syncs/tile (cp.async visibility
// + buffer-reuse protection — R10-proven protocol). 8-warp merge at end.
__device__ void attn_body(int task, const float* __restrict__ enc, float* sm) {
    int b = task >> 1, half = task & 1;
    float* buf = sm + SM_ABUF;
    int tid = threadIdx.x, w = tid >> 5, lane = tid & 31;
    const float* base = enc + ((size_t)b * L + (size_t)half * 512) * H;

    float qr[16];
    #pragma unroll
    for (int it = 0; it < 16; it++) qr[it] = g_s.q[b * H + lane + it * 32];

    copy_tile_async(buf, base, tid);
    CP_COMMIT();

    float m = -1e30f, Z = 0.f;
    float racc[16];
    #pragma unroll
    for (int i = 0; i < 16; i++) racc[i] = 0.f;

    #pragma unroll 1
    for (int st = 0; st < 16; st++) {
        const float* cur = buf + (st & 1) * (32 * 512);
        if (st < 15) {
            copy_tile_async(buf + ((st + 1) & 1) * (32 * 512),
                            base + (st + 1) * 32 * 512, tid);
            CP_COMMIT();
            cp_wait<1>();
        } else {
            cp_wait<0>();
        }
        __syncthreads();                    // all threads' copies visible
        float e[4];
        #pragma unroll
        for (int rr = 0; rr < 4; rr++) {
            const float* row = cur + (w * 4 + rr) * 512;
            float s = 0.f;
            #pragma unroll
            for (int it = 0; it < 16; it++) s += qr[it] * row[lane + it * 32];
            #pragma unroll
            for (int o = 16; o > 0; o >>= 1)
                s += __shfl_xor_sync(0xffffffffu, s, o);
            e[rr] = s;
        }
        float tmax = fmaxf(fmaxf(e[0], e[1]), fmaxf(e[2], e[3]));
        float mn = fmaxf(m, tmax);
        float scale = expf(m - mn);
        m = mn;
        float p0 = expf(e[0] - mn), p1 = expf(e[1] - mn);
        float p2 = expf(e[2] - mn), p3 = expf(e[3] - mn);
        Z = Z * scale + (p0 + p1) + (p2 + p3);
        const float* r0p = cur + (w * 4) * 512 + lane;
        #pragma unroll
        for (int i = 0; i < 16; i++) {
            int c = i * 32;
            racc[i] = racc[i] * scale + p0 * r0p[c] + p1 * r0p[512 + c]
                    + p2 * r0p[1024 + c] + p3 * r0p[1536 + c];
        }
        __syncthreads();                    // reads done before next issue
    }
    // merge 8 warps through the (now free) tile buffer
    float* mw = buf;            // 8
    float* zw = buf + 8;        // 8
    float* rs = buf + 64;       // 8 x 512
    if (lane == 0) { mw[w] = m; zw[w] = Z; }
    __syncthreads();
    float M = mw[0];
    #pragma unroll
    for (int i = 1; i < 8; i++) M = fmaxf(M, mw[i]);
    float sc = expf(m - M);
    #pragma unroll
    for (int i = 0; i < 16; i++) rs[w * 512 + lane + i * 32] = racc[i] * sc;
    __syncthreads();
    float r0 = 0.f, r1 = 0.f;
    #pragma unroll
    for (int w2 = 0; w2 < 8; w2++) {
        r0 += rs[w2 * 512 + tid];
        r1 += rs[w2 * 512 + tid + 256];
    }
    g_s.ar[(b * 2 + half) * H + tid] = r0;
    g_s.ar[(b * 2 + half) * H + tid + 256] = r1;
    if (tid == 0) {
        float Zt = 0.f;
        #pragma unroll
        for (int i = 0; i < 8; i++) Zt += zw[i] * expf(mw[i] - M);
        g_s.am[b * 2 + half] = M;
        g_s.az[b * 2 + half] = Zt;
    }
    __syncthreads();
}

__device__ void rwrite_body(int task) {
    int bb = task >> 1, j = ((task & 1) << 8) + threadIdx.x;
    float m0 = g_s.am[bb * 2], m1 = g_s.am[bb * 2 + 1];
    float mm = fmaxf(m0, m1);
    float z = expf(m0 - mm) * g_s.az[bb * 2]
            + expf(m1 - mm) * g_s.az[bb * 2 + 1];
    float w0 = expf(m0 - mm) / z, w1 = expf(m1 - mm) / z;
    g_s.r[bb * H + j] = w0 * g_s.ar[(bb * 2) * H + j]
                      + w1 * g_s.ar[(bb * 2 + 1) * H + j];
}

// ---------------------------------------------------------------------------
// Persistent decoder. Per step: S1'(att LSTM + prev MLP), S2'(rnn0 + prev
// logits), S3, S4(q), S5(attn), S6(rwrite) -> 6 barriers/step + tail.
// ---------------------------------------------------------------------------
__global__ void __launch_bounds__(256, 1)
decoder_kernel(int nblk,
               const void* __restrict__ yptr,
               const float* __restrict__ enc,
               const float* __restrict__ emb,
               const float* __restrict__ aWih, const float* __restrict__ aWhh,
               const float* __restrict__ abih, const float* __restrict__ abhh,
               const float* __restrict__ rWih, const float* __restrict__ rWhh,
               const float* __restrict__ rbih, const float* __restrict__ rbhh,
               const float* __restrict__ Wsw, const float* __restrict__ Wsb,
               const float* __restrict__ Whw, const float* __restrict__ Whb,
               const float* __restrict__ W1, const float* __restrict__ b1,
               const float* __restrict__ W2, const float* __restrict__ b2,
               float* __restrict__ out) {
    extern __shared__ __align__(16) float sm[];
    const int bid = blockIdx.x;
    unsigned ph = 0;

    // Preamble: P(256) A2(1024) w1b(256) EW(128) p0(2) cbias(8) b1p(2)
    for (int task = bid; task < 1676; task += nblk) {
        if (task < 256)
            tileP_body((task >> 4) * 32, (task & 15) * 32, Whw, Wsw, sm);
        else if (task < 1280) {
            int u = task - 256;
            tileAB_body(aWih, E + H, E, Whw, H, g_s.A2, H,
                        (u & 15) * 32, (u >> 4) * 32, sm);
        } else if (task < 1536) {
            int u = task - 1280;
            tileAB_body(W1, 2 * H, H, Whw, H, g_s.w1b, H,
                        (u & 15) * 32, (u >> 4) * 32, sm);
        } else if (task < 1664) {
            int u = task - 1536;
            tileEW_body(emb, aWih, abih, abhh, (u & 1) * 32, (u >> 1) * 32, sm);
        } else if (task < 1666) vec_p0(task - 1664, Whw, Wsb);
        else if (task < 1674) vec_cbias(task - 1666, aWih, Whb);
        else vec_b1p(task - 1674, W1, b1, Whb);
    }
    grid_sync(nblk, ph);

    for (int t = 0; t < S; t++) {
        int rp = t & 1, wp = rp ^ 1;
        const float* h2prev = g_s.h2[rp];   // == h2[wp(t-1)] for t > 0

        // S1': att LSTM (128) + MLP of step t-1 (128, t>0)
        {
            int ntask = t > 0 ? 256 : 128;
            for (int task = bid; task < ntask; task += nblk) {
                if (task < 128)
                    lstm_body(task * 4, 1, t, yptr, g_s.r, g_s.h0[rp],
                              g_s.c0[rp], g_s.A2, aWhh, nullptr, nullptr,
                              g_s.h0[wp], g_s.c0[wp], sm);
                else
                    linear_body<true>((task - 128) * 4, h2prev, H, g_s.r,
                                      W1, 2 * H, g_s.w1b, H, 2 * H,
                                      g_s.b1p, g_s.hidden, H, 0, sm);
            }
        }
        grid_sync(nblk, ph);

        // S2': rnn layer 0 (128) + logits of step t-1 (16, t>0)
        {
            int ntask = t > 0 ? 144 : 128;
            for (int task = bid; task < ntask; task += nblk) {
                if (task < 128)
                    lstm_body(task * 4, 0, t, nullptr, g_s.h0[wp], g_s.h1[rp],
                              g_s.c1[rp], rWih, rWhh, rbih, rbhh,
                              g_s.h1[wp], g_s.c1[wp], sm);
                else
                    linear_body<false>((task - 128) * 4, g_s.hidden, H, nullptr,
                                       W2, H, nullptr, 0, H,
                                       b2, out, S * V, (t - 1) * V, sm);
            }
        }
        grid_sync(nblk, ph);

        // S3: rnn layer 1
        for (int task = bid; task < 128; task += nblk)
            lstm_body(task * 4, 0, t, nullptr, g_s.h1[wp], g_s.h2[rp],
                      g_s.c2[rp], rWih + 4 * H * H, rWhh + 4 * H * H,
                      rbih + 4 * H, rbhh + 4 * H,
                      g_s.h2[wp], g_s.c2[wp], sm);
        grid_sync(nblk, ph);

        // S4: q = P @ h2 + p0
        for (int task = bid; task < 128; task += nblk)
            linear_body<false>(task * 4, g_s.h2[wp], H, nullptr,
                               g_s.P, H, nullptr, 0, H,
                               g_s.p0, g_s.q, H, 0, sm);
        grid_sync(nblk, ph);

        // S5: streamed flash attention
        for (int task = bid; task < 128; task += nblk)
            attn_body(task, enc, sm);
        grid_sync(nblk, ph);

        // S6: distributed softmax merge -> r
        for (int task = bid; task < 128; task += nblk)
            rwrite_body(task);
        grid_sync(nblk, ph);
    }

    // Tail: MLP + logits for t = 127 (h2[wp(127)] = h2[0])
    for (int task = bid; task < 128; task += nblk)
        linear_body<true>(task * 4, g_s.h2[0], H, g_s.r,
                          W1, 2 * H, g_s.w1b, H, 2 * H,
                          g_s.b1p, g_s.hidden, H, 0, sm);
    grid_sync(nblk, ph);
    for (int task = bid; task < 16; task += nblk)
        linear_body<false>(task * 4, g_s.hidden, H, nullptr,
                           W2, H, nullptr, 0, H,
                           b2, out, S * V, (S - 1) * V, sm);
}

// ---------------------------------------------------------------------------
extern "C" void kernel_launch(void* const* d_in, const int* in_sizes, int n_in,
                              void* d_out, int out_size) {
    const void*  y    = d_in[0];
    const float* enc  = (const float*)d_in[1];
    const float* emb  = (const float*)d_in[2];
    const float* aWih = (const float*)d_in[3];
    const float* aWhh = (const float*)d_in[4];
    const float* abih = (const float*)d_in[5];
    const float* abhh = (const float*)d_in[6];
    const float* rWih = (const float*)d_in[7];
    const float* rWhh = (const float*)d_in[8];
    const float* rbih = (const float*)d_in[9];
    const float* rbhh = (const float*)d_in[10];
    const float* Wsw  = (const float*)d_in[11];
    const float* Wsb  = (const float*)d_in[12];
    const float* Whw  = (const float*)d_in[13];
    const float* Whb  = (const float*)d_in[14];
    const float* W1   = (const float*)d_in[15];
    const float* b1   = (const float*)d_in[16];
    const float* W2   = (const float*)d_in[17];
    const float* b2   = (const float*)d_in[18];
    float* out = (float*)d_out;

    const int SMEM_BYTES = SMEM_FLOATS * (int)sizeof(float);  // ~128 KB
    static int configured = -1;
    if (configured < 0) {
        cudaFuncSetAttribute(decoder_kernel,
                             cudaFuncAttributeMaxDynamicSharedMemorySize,
                             SMEM_BYTES);
        configured = 1;
    }

    int dev = 0;
    cudaGetDevice(&dev);
    int sms = 128;
    cudaDeviceGetAttribute(&sms, cudaDevAttrMultiProcessorCount, dev);
    int nblk = sms < 128 ? sms : 128;

    init_kernel<<<(B * H + 255) / 256, 256>>>(y);
    decoder_kernel<<<nblk, 256, SMEM_BYTES>>>(
        nblk, y, enc, emb,
        aWih, aWhh, abih, abhh,
        rWih, rWhh, rbih, rbhh,
        Wsw, Wsb, Whw, Whb, W1, b1, W2, b2, out);
}

// round 16
// speedup vs baseline: 2.3966x; 1.0088x over previous
#include <cuda_runtime.h>
#include <cstdint>

#define B 64
#define S 128
#define L 1024
#define H 512
#define E 256
#define V 64

struct __align__(256) Scratch {
    float h0[2][B * H], c0[2][B * H];
    float h1[2][B * H], c1[2][B * H];
    float h2[2][B * H], c2[2][B * H];
    float r[B * H];
    float q[B * H];
    float hidden[B * H];
    float P[H * H], p0[H];
    float A2[4 * H * H], cbias[4 * H];
    float w1b[H * H], b1p[H];
    float EW[V * 4 * H];
    float am[B * 2], az[B * 2];
    float ar[B * 2 * H];
    int yflag;
};
__device__ Scratch g_s;
__device__ unsigned g_grp[8 * 32];
__device__ unsigned g_root;
__device__ unsigned g_rel[8 * 32];

__device__ __forceinline__ void fma2(unsigned long long& a,
                                     unsigned long long x,
                                     unsigned long long w) {
    asm("fma.rn.f32x2 %0, %1, %2, %3;" : "=l"(a) : "l"(x), "l"(w), "l"(a));
}
__device__ __forceinline__ float red2(unsigned long long a) {
    float lo, hi;
    asm("mov.b64 {%0,%1}, %2;" : "=f"(lo), "=f"(hi) : "l"(a));
    return lo + hi;
}

// Two-level grid barrier (R10-proven: full fences). nblk >= 8.
__device__ __forceinline__ void grid_sync(int nblk, unsigned& ph) {
    ph++;
    __syncthreads();
    if (threadIdx.x == 0) {
        int g = blockIdx.x & 7;
        unsigned ng = (unsigned)((nblk + 7 - g) >> 3);
        __threadfence();
        unsigned o = atomicAdd(&g_grp[g * 32], 1u);
        if (o + 1u == ng * ph) {
            __threadfence();
            unsigned ro = atomicAdd(&g_root, 1u);
            if (ro + 1u == 8u * ph) {
                __threadfence();
                #pragma unroll
                for (int i = 0; i < 8; i++)
                    *((volatile unsigned*)&g_rel[i * 32]) = ph;
            }
        }
        while (*((volatile unsigned*)&g_rel[g * 32]) < ph) { }
        __threadfence();
    }
    __syncthreads();
}

__device__ __forceinline__ void cp16(unsigned dst, const float* __restrict__ src) {
    asm volatile("cp.async.cg.shared.global [%0], [%1], 16;"
                 :: "r"(dst), "l"(src));
}
#define CP_COMMIT() asm volatile("cp.async.commit_group;")
template <int N>
__device__ __forceinline__ void cp_wait() {
    asm volatile("cp.async.wait_group %0;" :: "n"(N));
}
__device__ __forceinline__ void copy_tile_async(float* dst,
                                                const float* __restrict__ src,
                                                int tid) {
    unsigned d = (unsigned)__cvta_generic_to_shared(dst);
    #pragma unroll
    for (int u = 0; u < 16; u++) {
        int fo = (tid + u * 256) * 4;
        cp16(d + fo * 4, src + fo);
    }
}

#define XS_SZ (64 * 132)
#define SM_XS 0
#define SM_WS2 (2 * XS_SZ)
#define WS_SZ (16 * 128)
#define SM_ABUF 0
#define SMEM_FLOATS (2 * 32 * 512 + 32)

__global__ void init_kernel(const void* y) {
    int i = blockIdx.x * blockDim.x + threadIdx.x;
    if (i == 0) {
        g_root = 0u;
        const int* yi = (const int*)y;
        int f = 1;
        for (int k = 0; k < 128; k++)
            if (yi[2 * k + 1] != 0) { f = 0; break; }
        g_s.yflag = f;
    }
    if (i < 8 * 32) { g_grp[i] = 0u; g_rel[i] = 0u; }
    if (i < B * H) {
        g_s.h0[0][i] = 0.f; g_s.c0[0][i] = 0.f;
        g_s.h1[0][i] = 0.f; g_s.c1[0][i] = 0.f;
        g_s.h2[0][i] = 0.f; g_s.c2[0][i] = 0.f;
        g_s.r[i] = 0.f;
    }
}

// ---- preamble tile bodies (32x32, 256 thr) --------------------------------
__device__ void tileP_body(int j0, int k0, const float* __restrict__ Wh,
                           const float* __restrict__ Ws, float* sm) {
    float (*As)[33] = (float(*)[33])sm;
    float (*Bs)[33] = (float(*)[33])(sm + 32 * 33);
    int tid = threadIdx.x, tx = tid & 31, ty = tid >> 5;
    float acc[4] = {0.f, 0.f, 0.f, 0.f};
    for (int i0 = 0; i0 < H; i0 += 32) {
        #pragma unroll
        for (int u = 0; u < 4; u++) {
            int idx = tid + u * 256, ii = idx >> 5, cc = idx & 31;
            As[ii][cc] = Wh[(i0 + ii) * H + j0 + cc];
            Bs[ii][cc] = Ws[(i0 + ii) * H + k0 + cc];
        }
        __syncthreads();
        #pragma unroll
        for (int ii = 0; ii < 32; ii++) {
            float bv = Bs[ii][tx];
            #pragma unroll
            for (int rr = 0; rr < 4; rr++) acc[rr] += As[ii][ty + 8 * rr] * bv;
        }
        __syncthreads();
    }
    #pragma unroll
    for (int rr = 0; rr < 4; rr++)
        g_s.P[(j0 + ty + 8 * rr) * H + k0 + tx] = acc[rr];
    __syncthreads();
}

__device__ void tileAB_body(const float* __restrict__ A, int lda, int offA,
                            const float* __restrict__ Bm, int ldb,
                            float* __restrict__ Cm, int ldc,
                            int n0, int m0, float* sm) {
    float (*As)[33] = (float(*)[33])sm;
    float (*Bs)[33] = (float(*)[33])(sm + 32 * 33);
    int tid = threadIdx.x, tx = tid & 31, ty = tid >> 5;
    float acc[4] = {0.f, 0.f, 0.f, 0.f};
    for (int k0 = 0; k0 < H; k0 += 32) {
        #pragma unroll
        for (int u = 0; u < 4; u++) {
            int idx = tid + u * 256, rr = idx >> 5, cc = idx & 31;
            As[rr][cc] = A[(m0 + rr) * lda + offA + k0 + cc];
            Bs[rr][cc] = Bm[(k0 + rr) * ldb + n0 + cc];
        }
        __syncthreads();
        #pragma unroll
        for (int kk = 0; kk < 32; kk++) {
            float bv = Bs[kk][tx];
            #pragma unroll
            for (int rr = 0; rr < 4; rr++) acc[rr] += As[ty + 8 * rr][kk] * bv;
        }
        __syncthreads();
    }
    #pragma unroll
    for (int rr = 0; rr < 4; rr++)
        Cm[(m0 + ty + 8 * rr) * ldc + n0 + tx] = acc[rr];
    __syncthreads();
}

__device__ void tileEW_body(const float* __restrict__ emb,
                            const float* __restrict__ Wih,
                            const float* __restrict__ bih,
                            const float* __restrict__ bhh,
                            int v0, int j0, float* sm) {
    float (*As)[33] = (float(*)[33])sm;
    float (*Bs)[33] = (float(*)[33])(sm + 32 * 33);
    int tid = threadIdx.x, tx = tid & 31, ty = tid >> 5;
    float acc[4] = {0.f, 0.f, 0.f, 0.f};
    for (int k0 = 0; k0 < E; k0 += 32) {
        #pragma unroll
        for (int u = 0; u < 4; u++) {
            int idx = tid + u * 256, rr = idx >> 5, cc = idx & 31;
            As[rr][cc] = emb[(v0 + rr) * E + k0 + cc];
            Bs[rr][cc] = Wih[(j0 + rr) * (E + H) + k0 + cc];
        }
        __syncthreads();
        #pragma unroll
        for (int kk = 0; kk < 32; kk++) {
            #pragma unroll
            for (int rr = 0; rr < 4; rr++)
                acc[rr] += As[ty + 8 * rr][kk] * Bs[tx][kk];
        }
        __syncthreads();
    }
    #pragma unroll
    for (int rr = 0; rr < 4; rr++) {
        int v = v0 + ty + 8 * rr, j = j0 + tx;
        g_s.EW[v * (4 * H) + j] = acc[rr] + bih[j] + bhh[j];
    }
    __syncthreads();
}

__device__ void vec_p0(int part, const float* __restrict__ Wh,
                       const float* __restrict__ Wsb) {
    int j = part * 256 + threadIdx.x;
    float a = 0.f;
    for (int i = 0; i < H; i++) a += Wh[i * H + j] * Wsb[i];
    g_s.p0[j] = a;
}
__device__ void vec_cbias(int part, const float* __restrict__ Wih,
                          const float* __restrict__ Whb) {
    int j = part * 256 + threadIdx.x;
    float a = 0.f;
    for (int k = 0; k < H; k++) a += Wih[j * (E + H) + E + k] * Whb[k];
    g_s.cbias[j] = a;
}
__device__ void vec_b1p(int part, const float* __restrict__ W1,
                        const float* __restrict__ b1,
                        const float* __restrict__ Whb) {
    int n = part * 256 + threadIdx.x;
    float a = b1[n];
    for (int k = 0; k < H; k++) a += W1[n * 2 * H + H + k] * Whb[k];
    g_s.b1p[n] = a;
}

// ---- cp.async chunk staging ----------------------------------------------
__device__ __forceinline__ void x_issue(float* xsb, int tid, int k0,
                                        const float* __restrict__ xlo,
                                        const float* __restrict__ xhi) {
    const float* xb = (k0 < H) ? xlo + k0 : xhi + (k0 - H);
    unsigned xd = (unsigned)__cvta_generic_to_shared(xsb);
    #pragma unroll
    for (int u = 0; u < 8; u++) {
        int s = tid + u * 256;
        int bb = s >> 5, kk4 = (s & 31) * 4;
        cp16(xd + (bb * 132 + kk4) * 4, xb + bb * H + kk4);
    }
}
__device__ __forceinline__ void w16_issue(float* wsb, int tid, int k0, int jbase,
                                          const float* __restrict__ Wlo,
                                          const float* __restrict__ Whi) {
    const float* wb = (k0 < H) ? Wlo + k0 : Whi + (k0 - H);
    unsigned wd = (unsigned)__cvta_generic_to_shared(wsb);
    #pragma unroll
    for (int u = 0; u < 2; u++) {
        int s = tid + u * 256;
        int r16 = s >> 5, kk4 = (s & 31) * 4;
        int row = (r16 >> 2) * H + jbase + (r16 & 3);
        cp16(wd + (r16 * 128 + kk4) * 4, wb + row * H + kk4);
    }
}
__device__ __forceinline__ void w4_issue(float* wsb, int tid, int k0, int nbase,
                                         int K1,
                                         const float* __restrict__ Wa, int ldwa,
                                         const float* __restrict__ Wb, int ldwb) {
    if (tid < 128) {
        const float* wb; int ld;
        if (k0 < K1) { wb = Wa + (size_t)nbase * ldwa + k0; ld = ldwa; }
        else         { wb = Wb + (size_t)nbase * ldwb + (k0 - K1); ld = ldwb; }
        int rr = tid >> 5, kk4 = (tid & 31) * 4;
        unsigned wd = (unsigned)__cvta_generic_to_shared(wsb);
        cp16(wd + (rr * 128 + kk4) * 4, wb + rr * ld + kk4);
    }
}

// ---- LSTM body, K=1024 ----------------------------------------------------
__device__ void lstm_body(int jbase, int first, int t,
                          const void* __restrict__ yptr,
                          const float* __restrict__ xlo,
                          const float* __restrict__ hprev,
                          const float* __restrict__ cprev,
                          const float* __restrict__ Wlo,
                          const float* __restrict__ Whh,
                          const float* __restrict__ bih,
                          const float* __restrict__ bhh,
                          float* __restrict__ hout,
                          float* __restrict__ cout, float* sm) {
    int tid = threadIdx.x, b = tid & 63, jq = tid >> 6;

    x_issue(sm + SM_XS, tid, 0, xlo, hprev);
    w16_issue(sm + SM_WS2, tid, 0, jbase, Wlo, Whh);
    CP_COMMIT();

    unsigned long long a0 = 0ull, a1 = 0ull, a2 = 0ull, a3 = 0ull;
    #pragma unroll 1
    for (int ch = 0; ch < 8; ch++) {
        if (ch < 7) {
            int nb = (ch + 1) & 1;
            x_issue(sm + SM_XS + nb * XS_SZ, tid, (ch + 1) * 128, xlo, hprev);
            w16_issue(sm + SM_WS2 + nb * WS_SZ, tid, (ch + 1) * 128, jbase,
                      Wlo, Whh);
            CP_COMMIT();
            cp_wait<1>();
        } else {
            cp_wait<0>();
        }
        __syncthreads();
        const float* xs = sm + SM_XS + (ch & 1) * XS_SZ + b * 132;
        const float* ws = sm + SM_WS2 + (ch & 1) * WS_SZ;
        #pragma unroll
        for (int kk = 0; kk < 128; kk += 4) {
            ulonglong2 xv = *(const ulonglong2*)(xs + kk);
            ulonglong2 w0 = *(const ulonglong2*)(ws + jq * 128 + kk);
            ulonglong2 w1 = *(const ulonglong2*)(ws + (4 + jq) * 128 + kk);
            ulonglong2 w2 = *(const ulonglong2*)(ws + (8 + jq) * 128 + kk);
            ulonglong2 w3 = *(const ulonglong2*)(ws + (12 + jq) * 128 + kk);
            fma2(a0, xv.x, w0.x); fma2(a0, xv.y, w0.y);
            fma2(a1, xv.x, w1.x); fma2(a1, xv.y, w1.y);
            fma2(a2, xv.x, w2.x); fma2(a2, xv.y, w2.y);
            fma2(a3, xv.x, w3.x); fma2(a3, xv.y, w3.y);
        }
        __syncthreads();
    }

    int j = jbase + jq;
    float gi = red2(a0), gf = red2(a1), gg = red2(a2), go = red2(a3);
    if (first) {
        int yy = g_s.yflag ? (int)((const long long*)yptr)[b * S + t]
                           : ((const int*)yptr)[b * S + t];
        const float* ew = g_s.EW + yy * (4 * H);
        gi += ew[j];         gf += ew[j + H];
        gg += ew[j + 2 * H]; go += ew[j + 3 * H];
        if (t > 0) {
            gi += g_s.cbias[j];         gf += g_s.cbias[j + H];
            gg += g_s.cbias[j + 2 * H]; go += g_s.cbias[j + 3 * H];
        }
    } else {
        gi += bih[j] + bhh[j];
        gf += bih[j + H] + bhh[j + H];
        gg += bih[j + 2 * H] + bhh[j + 2 * H];
        go += bih[j + 3 * H] + bhh[j + 3 * H];
    }
    float si = 1.f / (1.f + expf(-gi));
    float sf = 1.f / (1.f + expf(-gf));
    float so = 1.f / (1.f + expf(-go));
    float cv = sf * cprev[b * H + j] + si * tanhf(gg);
    cout[b * H + j] = cv;
    hout[b * H + j] = so * tanhf(cv);
}

// ---- Linear body ----------------------------------------------------------
template <bool RELU>
__device__ void linear_body(int nbase, const float* __restrict__ x1, int K1,
                            const float* __restrict__ x2,
                            const float* __restrict__ Wa, int ldwa,
                            const float* __restrict__ Wb, int ldwb, int Ktot,
                            const float* __restrict__ bias,
                            float* __restrict__ outp, int ldo, int off,
                            float* sm) {
    int tid = threadIdx.x, b = tid & 63, nq = tid >> 6;
    int NCH = Ktot >> 7;

    x_issue(sm + SM_XS, tid, 0, x1, x2);
    w4_issue(sm + SM_WS2, tid, 0, nbase, K1, Wa, ldwa, Wb, ldwb);
    CP_COMMIT();

    unsigned long long acc = 0ull;
    #pragma unroll 1
    for (int ch = 0; ch < NCH; ch++) {
        if (ch + 1 < NCH) {
            int nb = (ch + 1) & 1;
            x_issue(sm + SM_XS + nb * XS_SZ, tid, (ch + 1) * 128, x1, x2);
            w4_issue(sm + SM_WS2 + nb * WS_SZ, tid, (ch + 1) * 128, nbase, K1,
                     Wa, ldwa, Wb, ldwb);
            CP_COMMIT();
            cp_wait<1>();
        } else {
            cp_wait<0>();
        }
        __syncthreads();
        const float* xs = sm + SM_XS + (ch & 1) * XS_SZ + b * 132;
        const float* ws = sm + SM_WS2 + (ch & 1) * WS_SZ + nq * 128;
        #pragma unroll
        for (int kk = 0; kk < 128; kk += 4) {
            ulonglong2 xv = *(const ulonglong2*)(xs + kk);
            ulonglong2 wv = *(const ulonglong2*)(ws + kk);
            fma2(acc, xv.x, wv.x); fma2(acc, xv.y, wv.y);
        }
        __syncthreads();
    }
    int n = nbase + nq;
    float a = red2(acc) + bias[n];
    if (RELU) a = fmaxf(a, 0.f);
    outp[b * ldo + off + n] = a;
}

// ---- Per-warp online-softmax flash attention (float4 lanes) ---------------
// task=(b,half): 512 rows in 16 tiles of 32. Each warp owns 4 rows/tile.
// Lane column set: j = lane*4 + g*128 + 0..3 (g=0..3) -> all smem traffic is
// LDS.128 (phase banks 4*lane mod 32: conflict-free). Two syncs/tile
// (cp.async visibility + buffer-reuse). 8-warp merge at end.
__device__ void attn_body(int task, const float* __restrict__ enc, float* sm) {
    int b = task >> 1, half = task & 1;
    float* buf = sm + SM_ABUF;
    int tid = threadIdx.x, w = tid >> 5, lane = tid & 31;
    const float* base = enc + ((size_t)b * L + (size_t)half * 512) * H;

    float4 q4[4];
    #pragma unroll
    for (int g = 0; g < 4; g++)
        q4[g] = ((const float4*)(g_s.q + b * H))[lane + g * 32];

    copy_tile_async(buf, base, tid);
    CP_COMMIT();

    float m = -1e30f, Z = 0.f;
    float4 racc[4];
    #pragma unroll
    for (int g = 0; g < 4; g++) racc[g] = make_float4(0.f, 0.f, 0.f, 0.f);

    #pragma unroll 1
    for (int st = 0; st < 16; st++) {
        const float* cur = buf + (st & 1) * (32 * 512);
        if (st < 15) {
            copy_tile_async(buf + ((st + 1) & 1) * (32 * 512),
                            base + (st + 1) * 32 * 512, tid);
            CP_COMMIT();
            cp_wait<1>();
        } else {
            cp_wait<0>();
        }
        __syncthreads();                    // all threads' copies visible
        float e[4];
        #pragma unroll
        for (int rr = 0; rr < 4; rr++) {
            const float4* row4 = (const float4*)(cur + (w * 4 + rr) * 512);
            float s = 0.f;
            #pragma unroll
            for (int g = 0; g < 4; g++) {
                float4 v = row4[lane + g * 32];
                s += q4[g].x * v.x + q4[g].y * v.y
                   + q4[g].z * v.z + q4[g].w * v.w;
            }
            #pragma unroll
            for (int o = 16; o > 0; o >>= 1)
                s += __shfl_xor_sync(0xffffffffu, s, o);
            e[rr] = s;
        }
        float tmax = fmaxf(fmaxf(e[0], e[1]), fmaxf(e[2], e[3]));
        float mn = fmaxf(m, tmax);
        float scale = expf(m - mn);
        m = mn;
        float p0 = expf(e[0] - mn), p1 = expf(e[1] - mn);
        float p2 = expf(e[2] - mn), p3 = expf(e[3] - mn);
        Z = Z * scale + (p0 + p1) + (p2 + p3);
        const float4* r04 = (const float4*)(cur + (w * 4) * 512);
        #pragma unroll
        for (int g = 0; g < 4; g++) {
            int c = lane + g * 32;
            float4 v0 = r04[c], v1 = r04[128 + c];
            float4 v2 = r04[256 + c], v3 = r04[384 + c];
            racc[g].x = racc[g].x * scale + p0 * v0.x + p1 * v1.x
                      + p2 * v2.x + p3 * v3.x;
            racc[g].y = racc[g].y * scale + p0 * v0.y + p1 * v1.y
                      + p2 * v2.y + p3 * v3.y;
            racc[g].z = racc[g].z * scale + p0 * v0.z + p1 * v1.z
                      + p2 * v2.z + p3 * v3.z;
            racc[g].w = racc[g].w * scale + p0 * v0.w + p1 * v1.w
                      + p2 * v2.w + p3 * v3.w;
        }
        __syncthreads();                    // reads done before next issue
    }
    // merge 8 warps through the (now free) tile buffer
    float* mw = buf;            // 8
    float* zw = buf + 8;        // 8
    float* rs = buf + 64;       // 8 x 512
    if (lane == 0) { mw[w] = m; zw[w] = Z; }
    __syncthreads();
    float M = mw[0];
    #pragma unroll
    for (int i = 1; i < 8; i++) M = fmaxf(M, mw[i]);
    float sc = expf(m - M);
    #pragma unroll
    for (int g = 0; g < 4; g++) {
        float4 v = make_float4(racc[g].x * sc, racc[g].y * sc,
                               racc[g].z * sc, racc[g].w * sc);
        ((float4*)(rs + w * 512))[lane + g * 32] = v;
    }
    __syncthreads();
    float r0 = 0.f, r1 = 0.f;
    #pragma unroll
    for (int w2 = 0; w2 < 8; w2++) {
        r0 += rs[w2 * 512 + tid];
        r1 += rs[w2 * 512 + tid + 256];
    }
    g_s.ar[(b * 2 + half) * H + tid] = r0;
    g_s.ar[(b * 2 + half) * H + tid + 256] = r1;
    if (tid == 0) {
        float Zt = 0.f;
        #pragma unroll
        for (int i = 0; i < 8; i++) Zt += zw[i] * expf(mw[i] - M);
        g_s.am[b * 2 + half] = M;
        g_s.az[b * 2 + half] = Zt;
    }
    __syncthreads();
}

__device__ void rwrite_body(int task) {
    int bb = task >> 1, j = ((task & 1) << 8) + threadIdx.x;
    float m0 = g_s.am[bb * 2], m1 = g_s.am[bb * 2 + 1];
    float mm = fmaxf(m0, m1);
    float z = expf(m0 - mm) * g_s.az[bb * 2]
            + expf(m1 - mm) * g_s.az[bb * 2 + 1];
    float w0 = expf(m0 - mm) / z, w1 = expf(m1 - mm) / z;
    g_s.r[bb * H + j] = w0 * g_s.ar[(bb * 2) * H + j]
                      + w1 * g_s.ar[(bb * 2 + 1) * H + j];
}

// ---------------------------------------------------------------------------
// Persistent decoder. Per step: S1'(att LSTM + prev MLP), S2'(rnn0 + prev
// logits), S3, S4(q), S5(attn), S6(rwrite) -> 6 barriers/step + tail.
// ---------------------------------------------------------------------------
__global__ void __launch_bounds__(256, 1)
decoder_kernel(int nblk,
               const void* __restrict__ yptr,
               const float* __restrict__ enc,
               const float* __restrict__ emb,
               const float* __restrict__ aWih, const float* __restrict__ aWhh,
               const float* __restrict__ abih, const float* __restrict__ abhh,
               const float* __restrict__ rWih, const float* __restrict__ rWhh,
               const float* __restrict__ rbih, const float* __restrict__ rbhh,
               const float* __restrict__ Wsw, const float* __restrict__ Wsb,
               const float* __restrict__ Whw, const float* __restrict__ Whb,
               const float* __restrict__ W1, const float* __restrict__ b1,
               const float* __restrict__ W2, const float* __restrict__ b2,
               float* __restrict__ out) {
    extern __shared__ __align__(16) float sm[];
    const int bid = blockIdx.x;
    unsigned ph = 0;

    // Preamble: P(256) A2(1024) w1b(256) EW(128) p0(2) cbias(8) b1p(2)
    for (int task = bid; task < 1676; task += nblk) {
        if (task < 256)
            tileP_body((task >> 4) * 32, (task & 15) * 32, Whw, Wsw, sm);
        else if (task < 1280) {
            int u = task - 256;
            tileAB_body(aWih, E + H, E, Whw, H, g_s.A2, H,
                        (u & 15) * 32, (u >> 4) * 32, sm);
        } else if (task < 1536) {
            int u = task - 1280;
            tileAB_body(W1, 2 * H, H, Whw, H, g_s.w1b, H,
                        (u & 15) * 32, (u >> 4) * 32, sm);
        } else if (task < 1664) {
            int u = task - 1536;
            tileEW_body(emb, aWih, abih, abhh, (u & 1) * 32, (u >> 1) * 32, sm);
        } else if (task < 1666) vec_p0(task - 1664, Whw, Wsb);
        else if (task < 1674) vec_cbias(task - 1666, aWih, Whb);
        else vec_b1p(task - 1674, W1, b1, Whb);
    }
    grid_sync(nblk, ph);

    for (int t = 0; t < S; t++) {
        int rp = t & 1, wp = rp ^ 1;
        const float* h2prev = g_s.h2[rp];   // == h2[wp(t-1)] for t > 0

        // S1': att LSTM (128) + MLP of step t-1 (128, t>0)
        {
            int ntask = t > 0 ? 256 : 128;
            for (int task = bid; task < ntask; task += nblk) {
                if (task < 128)
                    lstm_body(task * 4, 1, t, yptr, g_s.r, g_s.h0[rp],
                              g_s.c0[rp], g_s.A2, aWhh, nullptr, nullptr,
                              g_s.h0[wp], g_s.c0[wp], sm);
                else
                    linear_body<true>((task - 128) * 4, h2prev, H, g_s.r,
                                      W1, 2 * H, g_s.w1b, H, 2 * H,
                                      g_s.b1p, g_s.hidden, H, 0, sm);
            }
        }
        grid_sync(nblk, ph);

        // S2': rnn layer 0 (128) + logits of step t-1 (16, t>0)
        {
            int ntask = t > 0 ? 144 : 128;
            for (int task = bid; task < ntask; task += nblk) {
                if (task < 128)
                    lstm_body(task * 4, 0, t, nullptr, g_s.h0[wp], g_s.h1[rp],
                              g_s.c1[rp], rWih, rWhh, rbih, rbhh,
                              g_s.h1[wp], g_s.c1[wp], sm);
                else
                    linear_body<false>((task - 128) * 4, g_s.hidden, H, nullptr,
                                       W2, H, nullptr, 0, H,
                                       b2, out, S * V, (t - 1) * V, sm);
            }
        }
        grid_sync(nblk, ph);

        // S3: rnn layer 1
        for (int task = bid; task < 128; task += nblk)
            lstm_body(task * 4, 0, t, nullptr, g_s.h1[wp], g_s.h2[rp],
                      g_s.c2[rp], rWih + 4 * H * H, rWhh + 4 * H * H,
                      rbih + 4 * H, rbhh + 4 * H,
                      g_s.h2[wp], g_s.c2[wp], sm);
        grid_sync(nblk, ph);

        // S4: q = P @ h2 + p0
        for (int task = bid; task < 128; task += nblk)
            linear_body<false>(task * 4, g_s.h2[wp], H, nullptr,
                               g_s.P, H, nullptr, 0, H,
                               g_s.p0, g_s.q, H, 0, sm);
        grid_sync(nblk, ph);

        // S5: streamed flash attention
        for (int task = bid; task < 128; task += nblk)
            attn_body(task, enc, sm);
        grid_sync(nblk, ph);

        // S6: distributed softmax merge -> r
        for (int task = bid; task < 128; task += nblk)
            rwrite_body(task);
        grid_sync(nblk, ph);
    }

    // Tail: MLP + logits for t = 127 (h2[wp(127)] = h2[0])
    for (int task = bid; task < 128; task += nblk)
        linear_body<true>(task * 4, g_s.h2[0], H, g_s.r,
                          W1, 2 * H, g_s.w1b, H, 2 * H,
                          g_s.b1p, g_s.hidden, H, 0, sm);
    grid_sync(nblk, ph);
    for (int task = bid; task < 16; task += nblk)
        linear_body<false>(task * 4, g_s.hidden, H, nullptr,
                           W2, H, nullptr, 0, H,
                           b2, out, S * V, (S - 1) * V, sm);
}

// ---------------------------------------------------------------------------
extern "C" void kernel_launch(void* const* d_in, const int* in_sizes, int n_in,
                              void* d_out, int out_size) {
    const void*  y    = d_in[0];
    const float* enc  = (const float*)d_in[1];
    const float* emb  = (const float*)d_in[2];
    const float* aWih = (const float*)d_in[3];
    const float* aWhh = (const float*)d_in[4];
    const float* abih = (const float*)d_in[5];
    const float* abhh = (const float*)d_in[6];
    const float* rWih = (const float*)d_in[7];
    const float* rWhh = (const float*)d_in[8];
    const float* rbih = (const float*)d_in[9];
    const float* rbhh = (const float*)d_in[10];
    const float* Wsw  = (const float*)d_in[11];
    const float* Wsb  = (const float*)d_in[12];
    const float* Whw  = (const float*)d_in[13];
    const float* Whb  = (const float*)d_in[14];
    const float* W1   = (const float*)d_in[15];
    const float* b1   = (const float*)d_in[16];
    const float* W2   = (const float*)d_in[17];
    const float* b2   = (const float*)d_in[18];
    float* out = (float*)d_out;

    const int SMEM_BYTES = SMEM_FLOATS * (int)sizeof(float);  // ~128 KB
    static int configured = -1;
    if (configured < 0) {
        cudaFuncSetAttribute(decoder_kernel,
                             cudaFuncAttributeMaxDynamicSharedMemorySize,
                             SMEM_BYTES);
        configured = 1;
    }

    int dev = 0;
    cudaGetDevice(&dev);
    int sms = 128;
    cudaDeviceGetAttribute(&sms, cudaDevAttrMultiProcessorCount, dev);
    int nblk = sms < 128 ? sms : 128;

    init_kernel<<<(B * H + 255) / 256, 256>>>(y);
    decoder_kernel<<<nblk, 256, SMEM_BYTES>>>(
        nblk, y, enc, emb,
        aWih, aWhh, abih, abhh,
        rWih, rWhh, rbih, rbhh,
        Wsw, Wsb, Whw, Whb, W1, b1, W2, b2, out);
}